// round 2
// baseline (speedup 1.0000x reference)
#include <cuda_runtime.h>

// Shapes: B=8, C=256, N=1024, V=12, H=4, D=64. NV = N*V = 12288.
// Identity: attention output == v (softmax over j sums to 1; j only indexes attn),
// so the whole net is 4 masked-batchstat-BN 1x1 convs (GEMMs) + residuals.
//
// This round: packed f32x2 FFMA2 mainloop, BN fused into next GEMM's X load,
// double-buffered smem. 6 launches total.

#define NVC 12288
#define NB 8
#define CNT_INV (1.0f/98304.0f)
#define EPS 1e-5f

// Scratch (device globals: allocation-free rule)
__device__ float g_emb[NB * 64 * NVC];     // rawE (pre-BN output of layer e)
__device__ float g_bufa[NB * 256 * NVC];   // rawV, later rawF
__device__ float g_bufb[NB * 256 * NVC];   // rawO
__device__ float g_stats[2048];

__global__ void zero_stats() {
    int i = blockIdx.x * blockDim.x + threadIdx.x;
    if (i < 2048) g_stats[i] = 0.0f;
}

__device__ __forceinline__ unsigned long long dup2(float w) {
    unsigned long long r;
    asm("mov.b64 %0, {%1, %1};" : "=l"(r) : "f"(w));
    return r;
}
__device__ __forceinline__ void ffma2(unsigned long long& d,
                                      unsigned long long a,
                                      unsigned long long b) {
    asm("fma.rn.f32x2 %0, %1, %2, %0;" : "+l"(d) : "l"(a), "l"(b));
}
__device__ __forceinline__ float2 unpack2(unsigned long long v) {
    float2 r;
    asm("mov.b64 {%0, %1}, %2;" : "=f"(r.x), "=f"(r.y) : "l"(v));
    return r;
}

// MODE: 0 = RAW (X used directly), 1 = BN (X = mask? relu(raw*a+c) : 0),
//       2 = BN+RES (X = resid + (mask? relu(raw*a+c) : 0))
template<int M, int K, int BM, int BN, int MODE>
__global__ void __launch_bounds__(128)
gemm_fused(const float* __restrict__ X, const float* __restrict__ W,
           const float* __restrict__ bias, const float* __restrict__ mask,
           const float* __restrict__ pssum, const float* __restrict__ pssq,
           const float* __restrict__ pg, const float* __restrict__ pb,
           const float* __restrict__ resid,
           float* __restrict__ Y, float* __restrict__ ssum, float* __restrict__ ssq)
{
    constexpr int BK = 16, TM = 8, TN = 16;
    constexpr int THREADS = (BM / TM) * (BN / TN);
    static_assert(THREADS == 128, "bad tile");
    constexpr int KT  = K / BK;
    constexpr int XLD = BK * BN / (4 * THREADS);   // float4 X loads per thread
    constexpr int WLD = BM * BK / (4 * THREADS);   // float4 W loads per thread
    constexpr int C4  = BN / 4;

    __shared__ __align__(16) float Ws[2][BK][BM + 4];
    __shared__ __align__(16) float Xs[2][BK][BN];
    __shared__ __align__(16) float maskS[BN];
    __shared__ float aS[K], cS[K];
    __shared__ float rs[BM], rq[BM];

    const int b    = blockIdx.z;
    const int row0 = blockIdx.y * BM;
    const int col0 = blockIdx.x * BN;
    const int tid  = threadIdx.x;
    const int tx   = tid % (BN / TN);
    const int ty   = tid / (BN / TN);
    const int rbase = ty * TM;
    const int cbase = tx * TN;

    const float* Xb = X + (size_t)b * K * NVC + col0;
    const float* Rb = (MODE == 2) ? resid + (size_t)b * K * NVC + col0 : nullptr;
    const float* Mb = mask + (size_t)b * NVC + col0;
    float*       Yb = Y + (size_t)b * M * NVC + col0;

    // ---- block init: mask tile, BN coefficients, stat accumulators ----
    for (int l = tid; l < BN / 4; l += THREADS)
        *reinterpret_cast<float4*>(&maskS[l * 4]) =
            *reinterpret_cast<const float4*>(&Mb[l * 4]);
    if (MODE != 0) {
        for (int k = tid; k < K; k += THREADS) {
            float mu  = pssum[k] * CNT_INV;
            float var = fmaf(-mu, mu, pssq[k] * CNT_INV);
            float a   = pg[k] * rsqrtf(var + EPS);
            aS[k] = a;
            cS[k] = fmaf(-mu, a, pb[k]);
        }
    }
    for (int l = tid; l < BM; l += THREADS) { rs[l] = 0.0f; rq[l] = 0.0f; }
    __syncthreads();

    // ---- tile 0 load ----
    {
        float4 xr[XLD], fr[XLD], wr[WLD];
#pragma unroll
        for (int it = 0; it < XLD; it++) {
            int idx = tid + it * THREADS;
            int kk = idx / C4, c4 = idx % C4;
            xr[it] = *reinterpret_cast<const float4*>(&Xb[(size_t)kk * NVC + c4 * 4]);
            if (MODE == 2)
                fr[it] = *reinterpret_cast<const float4*>(&Rb[(size_t)kk * NVC + c4 * 4]);
        }
#pragma unroll
        for (int it = 0; it < WLD; it++) {
            int idx = tid + it * THREADS;
            int m = idx >> 2, kc = idx & 3;
            wr[it] = *reinterpret_cast<const float4*>(&W[(size_t)(row0 + m) * K + kc * 4]);
        }
#pragma unroll
        for (int it = 0; it < XLD; it++) {
            int idx = tid + it * THREADS;
            int kk = idx / C4, c4 = idx % C4;
            float4 v = xr[it];
            if (MODE != 0) {
                float a = aS[kk], c = cS[kk];
                float4 mk = *reinterpret_cast<const float4*>(&maskS[c4 * 4]);
                v.x = mk.x > 0.0f ? fmaxf(fmaf(v.x, a, c), 0.0f) : 0.0f;
                v.y = mk.y > 0.0f ? fmaxf(fmaf(v.y, a, c), 0.0f) : 0.0f;
                v.z = mk.z > 0.0f ? fmaxf(fmaf(v.z, a, c), 0.0f) : 0.0f;
                v.w = mk.w > 0.0f ? fmaxf(fmaf(v.w, a, c), 0.0f) : 0.0f;
                if (MODE == 2) {
                    v.x += fr[it].x; v.y += fr[it].y; v.z += fr[it].z; v.w += fr[it].w;
                }
            }
            *reinterpret_cast<float4*>(&Xs[0][kk][c4 * 4]) = v;
        }
#pragma unroll
        for (int it = 0; it < WLD; it++) {
            int idx = tid + it * THREADS;
            int m = idx >> 2, kc = idx & 3;
            Ws[0][kc * 4 + 0][m] = wr[it].x;
            Ws[0][kc * 4 + 1][m] = wr[it].y;
            Ws[0][kc * 4 + 2][m] = wr[it].z;
            Ws[0][kc * 4 + 3][m] = wr[it].w;
        }
    }
    __syncthreads();

    unsigned long long acc[TM][TN / 2];
#pragma unroll
    for (int i = 0; i < TM; i++)
#pragma unroll
        for (int j = 0; j < TN / 2; j++) acc[i][j] = 0ull;

    int cur = 0;
#pragma unroll 1
    for (int t = 0; t < KT; t++) {
        float4 xr[XLD], fr[XLD], wr[WLD];
        const int k0n = (t + 1) * BK;
        if (t + 1 < KT) {
#pragma unroll
            for (int it = 0; it < XLD; it++) {
                int idx = tid + it * THREADS;
                int kk = idx / C4, c4 = idx % C4;
                xr[it] = *reinterpret_cast<const float4*>(&Xb[(size_t)(k0n + kk) * NVC + c4 * 4]);
                if (MODE == 2)
                    fr[it] = *reinterpret_cast<const float4*>(&Rb[(size_t)(k0n + kk) * NVC + c4 * 4]);
            }
#pragma unroll
            for (int it = 0; it < WLD; it++) {
                int idx = tid + it * THREADS;
                int m = idx >> 2, kc = idx & 3;
                wr[it] = *reinterpret_cast<const float4*>(&W[(size_t)(row0 + m) * K + k0n + kc * 4]);
            }
        }

        // ---- compute on buffer `cur` ----
#pragma unroll
        for (int kk = 0; kk < BK; kk++) {
            float4 wa = *reinterpret_cast<const float4*>(&Ws[cur][kk][rbase]);
            float4 wb = *reinterpret_cast<const float4*>(&Ws[cur][kk][rbase + 4]);
            unsigned long long wd[TM];
            wd[0] = dup2(wa.x); wd[1] = dup2(wa.y); wd[2] = dup2(wa.z); wd[3] = dup2(wa.w);
            wd[4] = dup2(wb.x); wd[5] = dup2(wb.y); wd[6] = dup2(wb.z); wd[7] = dup2(wb.w);
            unsigned long long xp[TN / 2];
#pragma unroll
            for (int p = 0; p < TN / 4; p++) {
                ulonglong2 xq = *reinterpret_cast<const ulonglong2*>(&Xs[cur][kk][cbase + 4 * p]);
                xp[2 * p] = xq.x; xp[2 * p + 1] = xq.y;
            }
#pragma unroll
            for (int i = 0; i < TM; i++)
#pragma unroll
                for (int j = 0; j < TN / 2; j++)
                    ffma2(acc[i][j], wd[i], xp[j]);
        }

        if (t + 1 < KT) {
            int nxt = cur ^ 1;
#pragma unroll
            for (int it = 0; it < XLD; it++) {
                int idx = tid + it * THREADS;
                int kk = idx / C4, c4 = idx % C4;
                float4 v = xr[it];
                if (MODE != 0) {
                    float a = aS[k0n + kk], c = cS[k0n + kk];
                    float4 mk = *reinterpret_cast<const float4*>(&maskS[c4 * 4]);
                    v.x = mk.x > 0.0f ? fmaxf(fmaf(v.x, a, c), 0.0f) : 0.0f;
                    v.y = mk.y > 0.0f ? fmaxf(fmaf(v.y, a, c), 0.0f) : 0.0f;
                    v.z = mk.z > 0.0f ? fmaxf(fmaf(v.z, a, c), 0.0f) : 0.0f;
                    v.w = mk.w > 0.0f ? fmaxf(fmaf(v.w, a, c), 0.0f) : 0.0f;
                    if (MODE == 2) {
                        v.x += fr[it].x; v.y += fr[it].y; v.z += fr[it].z; v.w += fr[it].w;
                    }
                }
                *reinterpret_cast<float4*>(&Xs[nxt][kk][c4 * 4]) = v;
            }
#pragma unroll
            for (int it = 0; it < WLD; it++) {
                int idx = tid + it * THREADS;
                int m = idx >> 2, kc = idx & 3;
                Ws[nxt][kc * 4 + 0][m] = wr[it].x;
                Ws[nxt][kc * 4 + 1][m] = wr[it].y;
                Ws[nxt][kc * 4 + 2][m] = wr[it].z;
                Ws[nxt][kc * 4 + 3][m] = wr[it].w;
            }
            __syncthreads();
            cur = nxt;
        }
    }

    // ---- epilogue: bias, mask, raw store, per-channel stats ----
    float mloc[TN];
#pragma unroll
    for (int p = 0; p < TN / 4; p++)
        *reinterpret_cast<float4*>(&mloc[4 * p]) =
            *reinterpret_cast<const float4*>(&maskS[cbase + 4 * p]);

#pragma unroll
    for (int i = 0; i < TM; i++) {
        const int m = rbase + i;
        const float bv = __ldg(&bias[row0 + m]);
        float s = 0.0f, q = 0.0f;
        alignas(16) float yv[TN];
#pragma unroll
        for (int j = 0; j < TN / 2; j++) {
            float2 pr = unpack2(acc[i][j]);
            float y0 = (pr.x + bv) * mloc[2 * j];
            float y1 = (pr.y + bv) * mloc[2 * j + 1];
            yv[2 * j] = y0; yv[2 * j + 1] = y1;
            s += y0 + y1;
            q += y0 * y0 + y1 * y1;
        }
        float* yrow = Yb + (size_t)(row0 + m) * NVC + cbase;
#pragma unroll
        for (int p = 0; p < TN / 4; p++)
            *reinterpret_cast<float4*>(&yrow[4 * p]) =
                *reinterpret_cast<const float4*>(&yv[4 * p]);
        atomicAdd(&rs[m], s);
        atomicAdd(&rq[m], q);
    }
    __syncthreads();
    for (int l = tid; l < BM; l += THREADS) {
        atomicAdd(&ssum[row0 + l], rs[l]);
        atomicAdd(&ssq[row0 + l], rq[l]);
    }
}

// out = [feats + bnmask_o(rawO)] + bnmask_f(rawF)
__global__ void __launch_bounds__(256)
final_fuse(const float* __restrict__ rawO, const float* __restrict__ rawF,
           const float* __restrict__ feats, const float* __restrict__ mask,
           const float* __restrict__ st,
           const float* __restrict__ go, const float* __restrict__ bno,
           const float* __restrict__ gf, const float* __restrict__ bnf,
           float* __restrict__ out)
{
    size_t i = (size_t)blockIdx.x * blockDim.x + threadIdx.x;
    constexpr size_t TOT4 = (size_t)NB * 256 * NVC / 4;
    if (i >= TOT4) return;
    size_t e = i * 4;
    int col = (int)(e % NVC);
    size_t bm = e / NVC;
    int m = (int)(bm % 256);
    int b = (int)(bm / 256);

    float muo  = st[640 + m] * CNT_INV;
    float varo = fmaf(-muo, muo, st[896 + m] * CNT_INV);
    float ao   = go[m] * rsqrtf(varo + EPS);
    float co   = fmaf(-muo, ao, bno[m]);
    float muf  = st[1152 + m] * CNT_INV;
    float varf = fmaf(-muf, muf, st[1408 + m] * CNT_INV);
    float af   = gf[m] * rsqrtf(varf + EPS);
    float cf   = fmaf(-muf, af, bnf[m]);

    float4 o4 = *reinterpret_cast<const float4*>(rawO + e);
    float4 f4 = *reinterpret_cast<const float4*>(rawF + e);
    float4 ft = *reinterpret_cast<const float4*>(feats + e);
    float4 mk = *reinterpret_cast<const float4*>(mask + (size_t)b * NVC + col);

    float4 r;
    r.x = ft.x + (mk.x > 0.0f ? fmaxf(fmaf(o4.x, ao, co), 0.0f) : 0.0f)
               + (mk.x > 0.0f ? fmaxf(fmaf(f4.x, af, cf), 0.0f) : 0.0f);
    r.y = ft.y + (mk.y > 0.0f ? fmaxf(fmaf(o4.y, ao, co), 0.0f) : 0.0f)
               + (mk.y > 0.0f ? fmaxf(fmaf(f4.y, af, cf), 0.0f) : 0.0f);
    r.z = ft.z + (mk.z > 0.0f ? fmaxf(fmaf(o4.z, ao, co), 0.0f) : 0.0f)
               + (mk.z > 0.0f ? fmaxf(fmaf(f4.z, af, cf), 0.0f) : 0.0f);
    r.w = ft.w + (mk.w > 0.0f ? fmaxf(fmaf(o4.w, ao, co), 0.0f) : 0.0f)
               + (mk.w > 0.0f ? fmaxf(fmaf(f4.w, af, cf), 0.0f) : 0.0f);
    *reinterpret_cast<float4*>(out + e) = r;
}

extern "C" void kernel_launch(void* const* d_in, const int* in_sizes, int n_in,
                              void* d_out, int out_size)
{
    const float* feats = (const float*)d_in[0];
    const float* mask  = (const float*)d_in[1];
    const float* We    = (const float*)d_in[2];
    const float* be    = (const float*)d_in[3];
    const float* ge    = (const float*)d_in[4];
    const float* bne   = (const float*)d_in[5];
    const float* Wa    = (const float*)d_in[6];
    const float* ba    = (const float*)d_in[7];
    const float* ga    = (const float*)d_in[8];
    const float* bna   = (const float*)d_in[9];
    const float* Wo    = (const float*)d_in[10];
    const float* bo    = (const float*)d_in[11];
    const float* go    = (const float*)d_in[12];
    const float* bno   = (const float*)d_in[13];
    const float* Wf    = (const float*)d_in[14];
    const float* bf    = (const float*)d_in[15];
    const float* gf    = (const float*)d_in[16];
    const float* bnf   = (const float*)d_in[17];
    float* out = (float*)d_out;

    float *emb, *bufa, *bufb, *st;
    cudaGetSymbolAddress((void**)&emb,  g_emb);
    cudaGetSymbolAddress((void**)&bufa, g_bufa);
    cudaGetSymbolAddress((void**)&bufb, g_bufb);
    cudaGetSymbolAddress((void**)&st,   g_stats);

    zero_stats<<<8, 256>>>();

    // L1 (e): rawE = We @ feats + be, masked; stats -> st[0],st[64]
    gemm_fused<64, 256, 64, 256, 0><<<dim3(NVC / 256, 1, NB), 128>>>(
        feats, We, be, mask, nullptr, nullptr, nullptr, nullptr, nullptr,
        emb, st + 0, st + 64);

    // L2 (v-slice of a): X = bn_e(rawE); rawV = Wa_v @ X + ba_v, masked
    gemm_fused<256, 64, 128, 128, 1><<<dim3(NVC / 128, 2, NB), 128>>>(
        emb, Wa + 512 * 64, ba + 512, mask, st + 0, st + 64, ge, bne, nullptr,
        bufa, st + 128, st + 384);

    // L3 (o): X = bn_v(rawV); rawO = Wo @ X + bo, masked
    gemm_fused<256, 256, 128, 128, 1><<<dim3(NVC / 128, 2, NB), 128>>>(
        bufa, Wo, bo, mask, st + 128, st + 384, ga + 512, bna + 512, nullptr,
        bufb, st + 640, st + 896);

    // L4 (f): X = feats + bn_o(rawO); rawF = Wf @ X + bf, masked
    gemm_fused<256, 256, 128, 128, 2><<<dim3(NVC / 128, 2, NB), 128>>>(
        bufb, Wf, bf, mask, st + 640, st + 896, go, bno, feats,
        bufa, st + 1152, st + 1408);

    // out = (feats + bn_o(rawO)) + bn_f(rawF)
    final_fuse<<<(NB * 256 * NVC / 4 + 255) / 256, 256>>>(
        bufb, bufa, feats, mask, st, go, bno, gf, bnf, out);
}

// round 7
// speedup vs baseline: 1.2889x; 1.2889x over previous
#include <cuda_runtime.h>
#include <cstdint>

// Shapes: B=8, C=256, N=1024, V=12. NVC = N*V = 12288.
// Identity: attention output == v (softmax over j sums to 1; j only indexes attn),
// so the net is 4 masked-batchstat-BN 1x1 convs (GEMMs) + residuals.
// Round 7: round-6 packed f32x2 FFMA2 GEMM with the Y-store row0 bug fixed
// (rounds 4-6 all dropped row0 in the epilogue store -> rel_err 0.80).

#define NVC 12288
#define NB 8
#define CNT_INV (1.0f/98304.0f)
#define EPS 1e-5f

__device__ float g_emb[NB * 64 * NVC];
__device__ float g_bufa[NB * 256 * NVC];
__device__ float g_bufb[NB * 256 * NVC];
__device__ float g_stats[2048];

__global__ void zero_stats() {
    int i = blockIdx.x * blockDim.x + threadIdx.x;
    if (i < 2048) g_stats[i] = 0.0f;
}

__device__ __forceinline__ unsigned long long dup2(float w) {
    unsigned long long r;
    asm("mov.b64 %0, {%1, %1};" : "=l"(r) : "f"(w));
    return r;
}
__device__ __forceinline__ void ffma2(unsigned long long& d,
                                      unsigned long long a,
                                      unsigned long long b) {
    asm("fma.rn.f32x2 %0, %1, %2, %0;" : "+l"(d) : "l"(a), "l"(b));
}
__device__ __forceinline__ float2 unpack2(unsigned long long v) {
    float2 r;
    asm("mov.b64 {%0, %1}, %2;" : "=f"(r.x), "=f"(r.y) : "l"(v));
    return r;
}

// Y[b,m,col] = (sum_k W[m,k]*g(X)[b,k,col] + bias[m]) * mask, plus per-channel
// sum/sumsq. g(): MODE 0=identity, 1=BN+relu+mask, 2=that+resid.
// Tile: BM x 128, BK=32, 256 threads, thread tile TM x 8 (packed f32x2).
template<int M, int K, int BM, int TM, int MODE>
__global__ void __launch_bounds__(256, 2)
gemm_fused(const float* __restrict__ X, const float* __restrict__ W,
           const float* __restrict__ bias, const float* __restrict__ mask,
           const float* __restrict__ pssum, const float* __restrict__ pssq,
           const float* __restrict__ pg, const float* __restrict__ pb,
           const float* __restrict__ resid,
           float* __restrict__ Y, float* __restrict__ ssum, float* __restrict__ ssq)
{
    constexpr int BN = 128, BK = 32, TN = 8;
    constexpr int THREADS = (BM / TM) * (BN / TN);
    static_assert(THREADS == 256, "bad tile");
    constexpr int KT = K / BK;

    __shared__ __align__(16) float Ws[BK][BM + 4];
    __shared__ __align__(16) float Xs[BK][BN];
    __shared__ __align__(16) float maskS[BN];
    __shared__ float aS[K], cS[K];
    __shared__ float rs[BM], rq[BM];

    const int b    = blockIdx.z;
    const int row0 = blockIdx.y * BM;
    const int col0 = blockIdx.x * BN;
    const int tid  = threadIdx.x;
    const int tx   = tid & 15;             // BN/TN = 16
    const int ty   = tid >> 4;             // BM/TM = 16
    const int rbase = ty * TM;
    const int cbase = tx * TN;

    const float* Xb = X + (size_t)b * K * NVC + col0;
    const float* Rb = (MODE == 2) ? resid + (size_t)b * K * NVC + col0 : nullptr;
    const float* Mb = mask + (size_t)b * NVC + col0;
    float*       Yb = Y + (size_t)b * M * NVC + col0;

    // ---- block init: mask tile, BN coefficients, stat accumulators ----
    for (int i = tid; i < BN / 4; i += THREADS)
        reinterpret_cast<float4*>(maskS)[i] = reinterpret_cast<const float4*>(Mb)[i];
    if (MODE != 0) {
        for (int k = tid; k < K; k += THREADS) {
            float mu  = pssum[k] * CNT_INV;
            float var = fmaf(-mu, mu, pssq[k] * CNT_INV);
            float a   = pg[k] * rsqrtf(var + EPS);
            aS[k] = a;
            cS[k] = fmaf(-mu, a, pb[k]);
        }
    }
    for (int i = tid; i < BM; i += THREADS) { rs[i] = 0.0f; rq[i] = 0.0f; }
    __syncthreads();

    unsigned long long acc[TM][TN / 2];
#pragma unroll
    for (int i = 0; i < TM; i++)
#pragma unroll
        for (int j = 0; j < TN / 2; j++) acc[i][j] = 0ull;

#pragma unroll 1
    for (int t = 0; t < KT; t++) {
        const int k0 = t * BK;

        // ---- fill X tile [BK x BN] with fused transform ----
#pragma unroll
        for (int it = 0; it < BK * BN / (4 * THREADS); it++) {
            const int idx = tid + it * THREADS;
            const int kk = idx >> 5;                // BN/4 = 32 float4 per row
            const int c4 = (idx & 31) << 2;
            float4 v = *reinterpret_cast<const float4*>(Xb + (size_t)(k0 + kk) * NVC + c4);
            if (MODE != 0) {
                const float a = aS[k0 + kk], cc = cS[k0 + kk];
                float4 mk = *reinterpret_cast<const float4*>(&maskS[c4]);
                v.x = mk.x > 0.0f ? fmaxf(fmaf(v.x, a, cc), 0.0f) : 0.0f;
                v.y = mk.y > 0.0f ? fmaxf(fmaf(v.y, a, cc), 0.0f) : 0.0f;
                v.z = mk.z > 0.0f ? fmaxf(fmaf(v.z, a, cc), 0.0f) : 0.0f;
                v.w = mk.w > 0.0f ? fmaxf(fmaf(v.w, a, cc), 0.0f) : 0.0f;
                if (MODE == 2) {
                    float4 r = *reinterpret_cast<const float4*>(Rb + (size_t)(k0 + kk) * NVC + c4);
                    v.x += r.x; v.y += r.y; v.z += r.z; v.w += r.w;
                }
            }
            *reinterpret_cast<float4*>(&Xs[kk][c4]) = v;
        }
        // ---- fill W tile [BM x BK] transposed -> Ws[k][m] ----
#pragma unroll
        for (int it = 0; it < BM * BK / (4 * THREADS); it++) {
            const int idx = tid + it * THREADS;
            const int m  = idx >> 3;                // BK/4 = 8 float4 per row
            const int kc = idx & 7;
            float4 w = *reinterpret_cast<const float4*>(W + (size_t)(row0 + m) * K + k0 + kc * 4);
            Ws[kc * 4 + 0][m] = w.x;
            Ws[kc * 4 + 1][m] = w.y;
            Ws[kc * 4 + 2][m] = w.z;
            Ws[kc * 4 + 3][m] = w.w;
        }
        __syncthreads();

        // ---- compute ----
#pragma unroll 4
        for (int kk = 0; kk < BK; kk++) {
            unsigned long long wd[TM];
#pragma unroll
            for (int i = 0; i < TM; i += 4) {
                float4 wa = *reinterpret_cast<const float4*>(&Ws[kk][rbase + i]);
                wd[i + 0] = dup2(wa.x); wd[i + 1] = dup2(wa.y);
                wd[i + 2] = dup2(wa.z); wd[i + 3] = dup2(wa.w);
            }
            unsigned long long xp[TN / 2];
#pragma unroll
            for (int p = 0; p < TN / 4; p++) {
                ulonglong2 xq = *reinterpret_cast<const ulonglong2*>(&Xs[kk][cbase + 4 * p]);
                xp[2 * p] = xq.x; xp[2 * p + 1] = xq.y;
            }
#pragma unroll
            for (int i = 0; i < TM; i++)
#pragma unroll
                for (int j = 0; j < TN / 2; j++)
                    ffma2(acc[i][j], wd[i], xp[j]);
        }
        __syncthreads();
    }

    // ---- epilogue: bias + mask, store raw Y, per-channel stats ----
    alignas(16) float mloc[TN];
#pragma unroll
    for (int p = 0; p < TN / 4; p++)
        *reinterpret_cast<float4*>(&mloc[4 * p]) =
            *reinterpret_cast<const float4*>(&maskS[cbase + 4 * p]);

#pragma unroll
    for (int i = 0; i < TM; i++) {
        const int m = rbase + i;
        const float bv = __ldg(&bias[row0 + m]);
        float s = 0.0f, q = 0.0f;
        alignas(16) float yv[TN];
#pragma unroll
        for (int j = 0; j < TN / 2; j++) {
            float2 pr = unpack2(acc[i][j]);
            float y0 = (pr.x + bv) * mloc[2 * j];
            float y1 = (pr.y + bv) * mloc[2 * j + 1];
            yv[2 * j] = y0; yv[2 * j + 1] = y1;
            s += y0 + y1;
            q += y0 * y0 + y1 * y1;
        }
        // FIX: global row = row0 + m (rounds 4-6 dropped row0 here)
        float* yrow = Yb + (size_t)(row0 + m) * NVC + cbase;
#pragma unroll
        for (int p = 0; p < TN / 4; p++)
            *reinterpret_cast<float4*>(&yrow[4 * p]) =
                *reinterpret_cast<const float4*>(&yv[4 * p]);
        atomicAdd(&rs[m], s);
        atomicAdd(&rq[m], q);
    }
    __syncthreads();
    for (int i = tid; i < BM; i += THREADS) {
        atomicAdd(&ssum[row0 + i], rs[i]);
        atomicAdd(&ssq[row0 + i], rq[i]);
    }
}

// out = feats + bnmask_o(rawO) + bnmask_f(rawF)
__global__ void __launch_bounds__(256)
final_fuse(const float* __restrict__ rawO, const float* __restrict__ rawF,
           const float* __restrict__ feats, const float* __restrict__ mask,
           const float* __restrict__ st,
           const float* __restrict__ go, const float* __restrict__ bno,
           const float* __restrict__ gf, const float* __restrict__ bnf,
           float* __restrict__ out)
{
    size_t i = (size_t)blockIdx.x * blockDim.x + threadIdx.x;
    constexpr size_t TOT4 = (size_t)NB * 256 * NVC / 4;
    if (i >= TOT4) return;
    size_t e = i * 4;
    int col = (int)(e % NVC);
    size_t bm = e / NVC;
    int m = (int)(bm % 256);
    int b = (int)(bm / 256);

    float muo  = st[640 + m] * CNT_INV;
    float varo = fmaf(-muo, muo, st[896 + m] * CNT_INV);
    float ao   = go[m] * rsqrtf(varo + EPS);
    float co   = fmaf(-muo, ao, bno[m]);
    float muf  = st[1152 + m] * CNT_INV;
    float varf = fmaf(-muf, muf, st[1408 + m] * CNT_INV);
    float af   = gf[m] * rsqrtf(varf + EPS);
    float cf   = fmaf(-muf, af, bnf[m]);

    float4 o4 = *reinterpret_cast<const float4*>(rawO + e);
    float4 f4 = *reinterpret_cast<const float4*>(rawF + e);
    float4 ft = *reinterpret_cast<const float4*>(feats + e);
    float4 mk = *reinterpret_cast<const float4*>(mask + (size_t)b * NVC + col);

    float4 r;
    r.x = ft.x + (mk.x > 0.0f ? fmaxf(fmaf(o4.x, ao, co), 0.0f) + fmaxf(fmaf(f4.x, af, cf), 0.0f) : 0.0f);
    r.y = ft.y + (mk.y > 0.0f ? fmaxf(fmaf(o4.y, ao, co), 0.0f) + fmaxf(fmaf(f4.y, af, cf), 0.0f) : 0.0f);
    r.z = ft.z + (mk.z > 0.0f ? fmaxf(fmaf(o4.z, ao, co), 0.0f) + fmaxf(fmaf(f4.z, af, cf), 0.0f) : 0.0f);
    r.w = ft.w + (mk.w > 0.0f ? fmaxf(fmaf(o4.w, ao, co), 0.0f) + fmaxf(fmaf(f4.w, af, cf), 0.0f) : 0.0f);
    *reinterpret_cast<float4*>(out + e) = r;
}

extern "C" void kernel_launch(void* const* d_in, const int* in_sizes, int n_in,
                              void* d_out, int out_size)
{
    const float* feats = (const float*)d_in[0];
    const float* mask  = (const float*)d_in[1];
    const float* We    = (const float*)d_in[2];
    const float* be    = (const float*)d_in[3];
    const float* ge    = (const float*)d_in[4];
    const float* bne   = (const float*)d_in[5];
    const float* Wa    = (const float*)d_in[6];
    const float* ba    = (const float*)d_in[7];
    const float* ga    = (const float*)d_in[8];
    const float* bna   = (const float*)d_in[9];
    const float* Wo    = (const float*)d_in[10];
    const float* bo    = (const float*)d_in[11];
    const float* go    = (const float*)d_in[12];
    const float* bno   = (const float*)d_in[13];
    const float* Wf    = (const float*)d_in[14];
    const float* bf    = (const float*)d_in[15];
    const float* gf    = (const float*)d_in[16];
    const float* bnf   = (const float*)d_in[17];
    float* out = (float*)d_out;

    float *emb, *bufa, *bufb, *st;
    cudaGetSymbolAddress((void**)&emb,  g_emb);
    cudaGetSymbolAddress((void**)&bufa, g_bufa);
    cudaGetSymbolAddress((void**)&bufb, g_bufb);
    cudaGetSymbolAddress((void**)&st,   g_stats);

    zero_stats<<<8, 256>>>();

    // L1 (e): rawE = We @ feats + be, masked; stats -> st[0], st[64]
    gemm_fused<64, 256, 64, 4, 0><<<dim3(NVC / 128, 1, NB), 256>>>(
        feats, We, be, mask, nullptr, nullptr, nullptr, nullptr, nullptr,
        emb, st + 0, st + 64);

    // L2 (v-slice of a): X = bn_e(rawE); rawV = Wa_v @ X + ba_v, masked
    gemm_fused<256, 64, 128, 8, 1><<<dim3(NVC / 128, 2, NB), 256>>>(
        emb, Wa + 512 * 64, ba + 512, mask, st + 0, st + 64, ge, bne, nullptr,
        bufa, st + 128, st + 384);

    // L3 (o): X = bn_v(rawV); rawO = Wo @ X + bo, masked
    gemm_fused<256, 256, 128, 8, 1><<<dim3(NVC / 128, 2, NB), 256>>>(
        bufa, Wo, bo, mask, st + 128, st + 384, ga + 512, bna + 512, nullptr,
        bufb, st + 640, st + 896);

    // L4 (f): X = feats + bn_o(rawO); rawF = Wf @ X + bf, masked
    gemm_fused<256, 256, 128, 8, 2><<<dim3(NVC / 128, 2, NB), 256>>>(
        bufb, Wf, bf, mask, st + 640, st + 896, go, bno, feats,
        bufa, st + 1152, st + 1408);

    // out = feats + bn_o(rawO) + bn_f(rawF)
    final_fuse<<<(NB * 256 * NVC / 4 + 255) / 256, 256>>>(
        bufb, bufa, feats, mask, st, go, bno, gf, bnf, out);
}

// round 8
// speedup vs baseline: 2.6162x; 2.0298x over previous
#include <cuda_runtime.h>
#include <cuda_bf16.h>
#include <cstdint>

// Shapes: B=8, C=256, N=1024, V=12. NVC = N*V = 12288.
// Identity: attention output == v (softmax over j sums to 1; j only indexes attn),
// so the net is 4 masked-batchstat-BN 1x1 convs (GEMMs) + residuals.
// Round 8: split-bf16 mma.sync (Ah*Bh + Ah*Bl + Al*Bh), direct-LDS fragments
// (round 5 mainloop) + the row0 epilogue-store fix that made round 7 pass.

#define NVC 12288
#define NB 8
#define CNT_INV (1.0f/98304.0f)
#define EPS 1e-5f

__device__ float g_emb[NB * 64 * NVC];
__device__ float g_bufa[NB * 256 * NVC];
__device__ float g_bufb[NB * 256 * NVC];
__device__ float g_stats[2048];

__global__ void zero_stats() {
    int i = blockIdx.x * blockDim.x + threadIdx.x;
    if (i < 2048) g_stats[i] = 0.0f;
}

__device__ __forceinline__ void mma16816(float* d, const uint32_t* a, const uint32_t* b) {
    asm volatile("mma.sync.aligned.m16n8k16.row.col.f32.bf16.bf16.f32 "
        "{%0,%1,%2,%3}, {%4,%5,%6,%7}, {%8,%9}, {%0,%1,%2,%3};"
        : "+f"(d[0]), "+f"(d[1]), "+f"(d[2]), "+f"(d[3])
        : "r"(a[0]), "r"(a[1]), "r"(a[2]), "r"(a[3]), "r"(b[0]), "r"(b[1]));
}

__device__ __forceinline__ uint32_t ld32(const __nv_bfloat16* p) {
    return *reinterpret_cast<const uint32_t*>(p);
}
// pack two bf16 (k, k+stride) -> u32, low half = first (even k)
__device__ __forceinline__ uint32_t pack2(const __nv_bfloat16* p, int stride) {
    uint32_t lo = *reinterpret_cast<const unsigned short*>(p);
    uint32_t hi = *reinterpret_cast<const unsigned short*>(p + stride);
    return lo | (hi << 16);
}

__device__ __forceinline__ void split4(float4 v, uint2& hi, uint2& lo) {
    __nv_bfloat162 h0, h1, l0, l1;
    h0.x = __float2bfloat16(v.x); h0.y = __float2bfloat16(v.y);
    h1.x = __float2bfloat16(v.z); h1.y = __float2bfloat16(v.w);
    l0.x = __float2bfloat16(v.x - __bfloat162float(h0.x));
    l0.y = __float2bfloat16(v.y - __bfloat162float(h0.y));
    l1.x = __float2bfloat16(v.z - __bfloat162float(h1.x));
    l1.y = __float2bfloat16(v.w - __bfloat162float(h1.y));
    hi.x = *reinterpret_cast<uint32_t*>(&h0); hi.y = *reinterpret_cast<uint32_t*>(&h1);
    lo.x = *reinterpret_cast<uint32_t*>(&l0); lo.y = *reinterpret_cast<uint32_t*>(&l1);
}

// One layer: Y[b,m,col] = (sum_k W[m,k]*g(X)[b,k,col] + bias[m]) * mask, plus
// per-channel sum/sumsq. g(): MODE 0=identity, 1=BN+relu+mask, 2=that+resid.
template<int M, int K, int BM, int MODE>
__global__ void __launch_bounds__(256, 2)
mma_layer(const float* __restrict__ X, const float* __restrict__ W,
          const float* __restrict__ bias, const float* __restrict__ mask,
          const float* __restrict__ pssum, const float* __restrict__ pssq,
          const float* __restrict__ pg, const float* __restrict__ pb,
          const float* __restrict__ resid,
          float* __restrict__ Y, float* __restrict__ ssum, float* __restrict__ ssq)
{
    constexpr int BN = 128, BK = 32;
    constexpr int SA = BK + 8;       // 40 elems, 80B row stride
    constexpr int SB = BN + 8;       // 136 elems, 272B row stride
    constexpr int WM = BM / 2;
    constexpr int MTI = WM / 16;
    constexpr int NCH = K / BK;

    __shared__ __align__(16) __nv_bfloat16 Ah[BM][SA];
    __shared__ __align__(16) __nv_bfloat16 Al[BM][SA];
    __shared__ __align__(16) __nv_bfloat16 Bh[BK][SB];
    __shared__ __align__(16) __nv_bfloat16 Bl[BK][SB];
    __shared__ __align__(16) float maskS[BN];
    __shared__ float aS[K], cS[K];
    __shared__ float rs[BM], rq[BM];

    const int b = blockIdx.z, row0 = blockIdx.y * BM, col0 = blockIdx.x * BN;
    const int tid = threadIdx.x, wid = tid >> 5, lid = tid & 31;
    const int warp_m = wid >> 2, warp_n = wid & 3;
    const int g = lid >> 2, t = lid & 3;

    const float* Xb = X + (size_t)b * K * NVC + col0;
    const float* Rb = (MODE == 2) ? resid + (size_t)b * K * NVC + col0 : nullptr;
    const float* Mb = mask + (size_t)b * NVC + col0;
    float*       Yb = Y + (size_t)b * M * NVC + col0;

    for (int i = tid; i < BN / 4; i += 256)
        reinterpret_cast<float4*>(maskS)[i] = reinterpret_cast<const float4*>(Mb)[i];
    if (MODE != 0) {
        for (int k = tid; k < K; k += 256) {
            float mu  = pssum[k] * CNT_INV;
            float var = fmaf(-mu, mu, pssq[k] * CNT_INV);
            float a   = pg[k] * rsqrtf(var + EPS);
            aS[k] = a;
            cS[k] = fmaf(-mu, a, pb[k]);
        }
    }
    for (int i = tid; i < BM; i += 256) { rs[i] = 0.0f; rq[i] = 0.0f; }
    __syncthreads();

    float acc[MTI][4][4];
#pragma unroll
    for (int mt = 0; mt < MTI; mt++)
#pragma unroll
        for (int nt = 0; nt < 4; nt++)
#pragma unroll
            for (int r = 0; r < 4; r++) acc[mt][nt][r] = 0.0f;

#pragma unroll 1
    for (int ch = 0; ch < NCH; ch++) {
        const int k0 = ch * BK;

        // ---- fill B (X chunk): [BK k][BN cols], BN-transform fused ----
#pragma unroll
        for (int i = tid; i < BK * BN / 4; i += 256) {
            const int kk = i >> 5;
            const int c4 = (i & 31) << 2;
            float4 v = *reinterpret_cast<const float4*>(Xb + (size_t)(k0 + kk) * NVC + c4);
            if (MODE != 0) {
                const float a = aS[k0 + kk], cc = cS[k0 + kk];
                float4 mk = *reinterpret_cast<const float4*>(&maskS[c4]);
                v.x = mk.x > 0.0f ? fmaxf(fmaf(v.x, a, cc), 0.0f) : 0.0f;
                v.y = mk.y > 0.0f ? fmaxf(fmaf(v.y, a, cc), 0.0f) : 0.0f;
                v.z = mk.z > 0.0f ? fmaxf(fmaf(v.z, a, cc), 0.0f) : 0.0f;
                v.w = mk.w > 0.0f ? fmaxf(fmaf(v.w, a, cc), 0.0f) : 0.0f;
                if (MODE == 2) {
                    float4 r = *reinterpret_cast<const float4*>(Rb + (size_t)(k0 + kk) * NVC + c4);
                    v.x += r.x; v.y += r.y; v.z += r.z; v.w += r.w;
                }
            }
            uint2 hi, lo;
            split4(v, hi, lo);
            *reinterpret_cast<uint2*>(&Bh[kk][c4]) = hi;
            *reinterpret_cast<uint2*>(&Bl[kk][c4]) = lo;
        }
        // ---- fill A (W chunk): [BM m][BK k] ----
#pragma unroll
        for (int i = tid; i < BM * BK / 4; i += 256) {
            const int m  = i >> 3;
            const int kq = (i & 7) << 2;
            float4 w = *reinterpret_cast<const float4*>(W + (size_t)(row0 + m) * K + k0 + kq);
            uint2 hi, lo;
            split4(w, hi, lo);
            *reinterpret_cast<uint2*>(&Ah[m][kq]) = hi;
            *reinterpret_cast<uint2*>(&Al[m][kq]) = lo;
        }
        __syncthreads();

        // ---- compute: 2 k16 steps, fragments via direct LDS ----
#pragma unroll
        for (int ks = 0; ks < 2; ks++) {
            const int kb = ks * 16;
            // B fragments: b0 = pack(B[kb+2t][n], B[kb+2t+1][n]); b1 = +8 k
            uint32_t bhf[4][2], blf[4][2];
#pragma unroll
            for (int nt = 0; nt < 4; nt++) {
                const int n = warp_n * 32 + nt * 8 + g;
                const __nv_bfloat16* ph = &Bh[kb + 2 * t][n];
                const __nv_bfloat16* pl = &Bl[kb + 2 * t][n];
                bhf[nt][0] = pack2(ph, SB);
                bhf[nt][1] = pack2(ph + 8 * SB, SB);
                blf[nt][0] = pack2(pl, SB);
                blf[nt][1] = pack2(pl + 8 * SB, SB);
            }
#pragma unroll
            for (int mt = 0; mt < MTI; mt++) {
                const int m0 = warp_m * WM + mt * 16;
                // A fragments: a0 = (row g, k 2t,2t+1), a1 = (row g+8, same k),
                //              a2 = (row g, k+8),       a3 = (row g+8, k+8)
                const __nv_bfloat16* qh = &Ah[m0 + g][kb + 2 * t];
                const __nv_bfloat16* ql = &Al[m0 + g][kb + 2 * t];
                uint32_t ah[4], al[4];
                ah[0] = ld32(qh);
                ah[1] = ld32(qh + 8 * SA);
                ah[2] = ld32(qh + 8);
                ah[3] = ld32(qh + 8 * SA + 8);
                al[0] = ld32(ql);
                al[1] = ld32(ql + 8 * SA);
                al[2] = ld32(ql + 8);
                al[3] = ld32(ql + 8 * SA + 8);
#pragma unroll
                for (int nt = 0; nt < 4; nt++) {
                    mma16816(acc[mt][nt], ah, bhf[nt]);
                    mma16816(acc[mt][nt], ah, blf[nt]);
                    mma16816(acc[mt][nt], al, bhf[nt]);
                }
            }
        }
        __syncthreads();
    }

    // ---- epilogue: bias + mask, store raw Y, per-row stats ----
#pragma unroll
    for (int mt = 0; mt < MTI; mt++) {
#pragma unroll
        for (int h = 0; h < 2; h++) {
            const int rowl = warp_m * WM + mt * 16 + h * 8 + g;
            const float bv = __ldg(&bias[row0 + rowl]);
            float s = 0.0f, q = 0.0f;
            // FIX (round-7 lesson): global row = row0 + rowl
            float* yrow = Yb + (size_t)(row0 + rowl) * NVC;
#pragma unroll
            for (int nt = 0; nt < 4; nt++) {
                const int coll = warp_n * 32 + nt * 8 + t * 2;
                float y0 = (acc[mt][nt][h * 2 + 0] + bv) * maskS[coll];
                float y1 = (acc[mt][nt][h * 2 + 1] + bv) * maskS[coll + 1];
                s += y0 + y1;
                q += y0 * y0 + y1 * y1;
                float2 o; o.x = y0; o.y = y1;
                *reinterpret_cast<float2*>(yrow + coll) = o;
            }
            s += __shfl_xor_sync(0xFFFFFFFF, s, 1);
            s += __shfl_xor_sync(0xFFFFFFFF, s, 2);
            q += __shfl_xor_sync(0xFFFFFFFF, q, 1);
            q += __shfl_xor_sync(0xFFFFFFFF, q, 2);
            if (t == 0) {
                atomicAdd(&rs[rowl], s);
                atomicAdd(&rq[rowl], q);
            }
        }
    }
    __syncthreads();
    for (int i = tid; i < BM; i += 256) {
        atomicAdd(&ssum[row0 + i], rs[i]);
        atomicAdd(&ssq[row0 + i], rq[i]);
    }
}

// out = feats + bnmask_o(rawO) + bnmask_f(rawF)
__global__ void __launch_bounds__(256)
final_fuse(const float* __restrict__ rawO, const float* __restrict__ rawF,
           const float* __restrict__ feats, const float* __restrict__ mask,
           const float* __restrict__ st,
           const float* __restrict__ go, const float* __restrict__ bno,
           const float* __restrict__ gf, const float* __restrict__ bnf,
           float* __restrict__ out)
{
    size_t i = (size_t)blockIdx.x * blockDim.x + threadIdx.x;
    constexpr size_t TOT4 = (size_t)NB * 256 * NVC / 4;
    if (i >= TOT4) return;
    size_t e = i * 4;
    int col = (int)(e % NVC);
    size_t bm = e / NVC;
    int m = (int)(bm % 256);
    int b = (int)(bm / 256);

    float muo  = st[640 + m] * CNT_INV;
    float varo = fmaf(-muo, muo, st[896 + m] * CNT_INV);
    float ao   = go[m] * rsqrtf(varo + EPS);
    float co   = fmaf(-muo, ao, bno[m]);
    float muf  = st[1152 + m] * CNT_INV;
    float varf = fmaf(-muf, muf, st[1408 + m] * CNT_INV);
    float af   = gf[m] * rsqrtf(varf + EPS);
    float cf   = fmaf(-muf, af, bnf[m]);

    float4 o4 = *reinterpret_cast<const float4*>(rawO + e);
    float4 f4 = *reinterpret_cast<const float4*>(rawF + e);
    float4 ft = *reinterpret_cast<const float4*>(feats + e);
    float4 mk = *reinterpret_cast<const float4*>(mask + (size_t)b * NVC + col);

    float4 r;
    r.x = ft.x + (mk.x > 0.0f ? fmaxf(fmaf(o4.x, ao, co), 0.0f) + fmaxf(fmaf(f4.x, af, cf), 0.0f) : 0.0f);
    r.y = ft.y + (mk.y > 0.0f ? fmaxf(fmaf(o4.y, ao, co), 0.0f) + fmaxf(fmaf(f4.y, af, cf), 0.0f) : 0.0f);
    r.z = ft.z + (mk.z > 0.0f ? fmaxf(fmaf(o4.z, ao, co), 0.0f) + fmaxf(fmaf(f4.z, af, cf), 0.0f) : 0.0f);
    r.w = ft.w + (mk.w > 0.0f ? fmaxf(fmaf(o4.w, ao, co), 0.0f) + fmaxf(fmaf(f4.w, af, cf), 0.0f) : 0.0f);
    *reinterpret_cast<float4*>(out + e) = r;
}

extern "C" void kernel_launch(void* const* d_in, const int* in_sizes, int n_in,
                              void* d_out, int out_size)
{
    const float* feats = (const float*)d_in[0];
    const float* mask  = (const float*)d_in[1];
    const float* We    = (const float*)d_in[2];
    const float* be    = (const float*)d_in[3];
    const float* ge    = (const float*)d_in[4];
    const float* bne   = (const float*)d_in[5];
    const float* Wa    = (const float*)d_in[6];
    const float* ba    = (const float*)d_in[7];
    const float* ga    = (const float*)d_in[8];
    const float* bna   = (const float*)d_in[9];
    const float* Wo    = (const float*)d_in[10];
    const float* bo    = (const float*)d_in[11];
    const float* go    = (const float*)d_in[12];
    const float* bno   = (const float*)d_in[13];
    const float* Wf    = (const float*)d_in[14];
    const float* bf    = (const float*)d_in[15];
    const float* gf    = (const float*)d_in[16];
    const float* bnf   = (const float*)d_in[17];
    float* out = (float*)d_out;

    float *emb, *bufa, *bufb, *st;
    cudaGetSymbolAddress((void**)&emb,  g_emb);
    cudaGetSymbolAddress((void**)&bufa, g_bufa);
    cudaGetSymbolAddress((void**)&bufb, g_bufb);
    cudaGetSymbolAddress((void**)&st,   g_stats);

    zero_stats<<<8, 256>>>();

    // L1 (e): rawE = We @ feats + be, masked
    mma_layer<64, 256, 64, 0><<<dim3(NVC / 128, 1, NB), 256>>>(
        feats, We, be, mask, nullptr, nullptr, nullptr, nullptr, nullptr,
        emb, st + 0, st + 64);

    // L2 (v-slice of a): X = bn_e(rawE); rawV = Wa_v @ X + ba_v, masked
    mma_layer<256, 64, 128, 1><<<dim3(NVC / 128, 2, NB), 256>>>(
        emb, Wa + 512 * 64, ba + 512, mask, st + 0, st + 64, ge, bne, nullptr,
        bufa, st + 128, st + 384);

    // L3 (o): X = bn_v(rawV); rawO = Wo @ X + bo, masked
    mma_layer<256, 256, 128, 1><<<dim3(NVC / 128, 2, NB), 256>>>(
        bufa, Wo, bo, mask, st + 128, st + 384, ga + 512, bna + 512, nullptr,
        bufb, st + 640, st + 896);

    // L4 (f): X = feats + bn_o(rawO); rawF = Wf @ X + bf, masked
    mma_layer<256, 256, 128, 2><<<dim3(NVC / 128, 2, NB), 256>>>(
        bufb, Wf, bf, mask, st + 640, st + 896, go, bno, feats,
        bufa, st + 1152, st + 1408);

    // out = feats + bn_o(rawO) + bn_f(rawF)
    final_fuse<<<(NB * 256 * NVC / 4 + 255) / 256, 256>>>(
        bufb, bufa, feats, mask, st, go, bno, gf, bnf, out);
}

// round 9
// speedup vs baseline: 2.7615x; 1.0556x over previous
#include <cuda_runtime.h>
#include <cuda_bf16.h>
#include <cstdint>

// Shapes: B=8, C=256, N=1024, V=12. NVC = N*V = 12288.
// Identity: attention output == v (softmax over j sums to 1; j only indexes attn),
// so the net is 4 masked-batchstat-BN 1x1 convs (GEMMs) + residuals.
// Round 9: round-8 split-bf16 mma.sync pipeline +
//   (a) weights pre-split once into global bf16 hi/lo planes; W tile fill is
//       pure cp.async (overlapped with X fill),
//   (b) packed cvt.rn.bf16x2 split for the X transform.

#define NVC 12288
#define NB 8
#define CNT_INV (1.0f/98304.0f)
#define EPS 1e-5f

__device__ float g_emb[NB * 64 * NVC];
__device__ float g_bufa[NB * 256 * NVC];
__device__ float g_bufb[NB * 256 * NVC];
__device__ float g_stats[2048];
// pre-split weight planes: We[16384] | Wa_v[16384] | Wo[65536] | Wf[65536]
__device__ __nv_bfloat16 g_whi[163840];
__device__ __nv_bfloat16 g_wlo[163840];

#define WOFF_E  0
#define WOFF_A  16384
#define WOFF_O  32768
#define WOFF_F  98304

__global__ void zero_stats() {
    int i = blockIdx.x * blockDim.x + threadIdx.x;
    if (i < 2048) g_stats[i] = 0.0f;
}

// Split the 4 weight matrices (Wa: v-slice rows [512,768)) into bf16 hi/lo planes.
__global__ void split_weights(const float* __restrict__ We, const float* __restrict__ Wa,
                              const float* __restrict__ Wo, const float* __restrict__ Wf)
{
    int i = blockIdx.x * blockDim.x + threadIdx.x;
    if (i >= 163840) return;
    float w;
    if (i < 16384)       w = We[i];
    else if (i < 32768)  w = Wa[512 * 64 + (i - 16384)];
    else if (i < 98304)  w = Wo[i - 32768];
    else                 w = Wf[i - 98304];
    __nv_bfloat16 h = __float2bfloat16(w);
    g_whi[i] = h;
    g_wlo[i] = __float2bfloat16(w - __bfloat162float(h));
}

__device__ __forceinline__ uint32_t smem_u32(const void* p) {
    uint32_t a;
    asm("{ .reg .u64 t; cvta.to.shared.u64 t, %1; cvt.u32.u64 %0, t; }" : "=r"(a) : "l"(p));
    return a;
}
__device__ __forceinline__ void cp_async16(uint32_t dst, const void* src) {
    asm volatile("cp.async.cg.shared.global [%0], [%1], 16;" :: "r"(dst), "l"(src));
}
#define CP_COMMIT() asm volatile("cp.async.commit_group;" ::: "memory")
#define CP_WAIT0()  asm volatile("cp.async.wait_group 0;" ::: "memory")

__device__ __forceinline__ void mma16816(float* d, const uint32_t* a, const uint32_t* b) {
    asm volatile("mma.sync.aligned.m16n8k16.row.col.f32.bf16.bf16.f32 "
        "{%0,%1,%2,%3}, {%4,%5,%6,%7}, {%8,%9}, {%0,%1,%2,%3};"
        : "+f"(d[0]), "+f"(d[1]), "+f"(d[2]), "+f"(d[3])
        : "r"(a[0]), "r"(a[1]), "r"(a[2]), "r"(a[3]), "r"(b[0]), "r"(b[1]));
}

__device__ __forceinline__ uint32_t ld32(const __nv_bfloat16* p) {
    return *reinterpret_cast<const uint32_t*>(p);
}
__device__ __forceinline__ uint32_t pack2(const __nv_bfloat16* p, int stride) {
    uint32_t lo = *reinterpret_cast<const unsigned short*>(p);
    uint32_t hi = *reinterpret_cast<const unsigned short*>(p + stride);
    return lo | (hi << 16);
}
// packed bf16x2 cvt: low half = cvt(l), high half = cvt(h)
__device__ __forceinline__ uint32_t cvt2(float h, float l) {
    uint32_t r;
    asm("cvt.rn.bf16x2.f32 %0, %1, %2;" : "=r"(r) : "f"(h), "f"(l));
    return r;
}
// split float4 -> bf16 hi/lo pairs via packed cvt + shift reconstruction
__device__ __forceinline__ void split4f(float4 v, uint2& hi, uint2& lo) {
    uint32_t h01 = cvt2(v.y, v.x);
    uint32_t h23 = cvt2(v.w, v.z);
    float f0 = __uint_as_float(h01 << 16);
    float f1 = __uint_as_float(h01 & 0xFFFF0000u);
    float f2 = __uint_as_float(h23 << 16);
    float f3 = __uint_as_float(h23 & 0xFFFF0000u);
    uint32_t l01 = cvt2(v.y - f1, v.x - f0);
    uint32_t l23 = cvt2(v.w - f3, v.z - f2);
    hi.x = h01; hi.y = h23;
    lo.x = l01; lo.y = l23;
}

// One layer: Y[b,m,col] = (sum_k W[m,k]*g(X)[b,k,col] + bias[m]) * mask, plus
// per-channel sum/sumsq. g(): MODE 0=identity, 1=BN+relu+mask, 2=that+resid.
template<int M, int K, int BM, int MODE>
__global__ void __launch_bounds__(256, 2)
mma_layer(const float* __restrict__ X,
          const __nv_bfloat16* __restrict__ Whi, const __nv_bfloat16* __restrict__ Wlo,
          const float* __restrict__ bias, const float* __restrict__ mask,
          const float* __restrict__ pssum, const float* __restrict__ pssq,
          const float* __restrict__ pg, const float* __restrict__ pb,
          const float* __restrict__ resid,
          float* __restrict__ Y, float* __restrict__ ssum, float* __restrict__ ssq)
{
    constexpr int BN = 128, BK = 32;
    constexpr int SA = BK + 8;       // 40 elems, 80B row stride (80 % 16 == 0)
    constexpr int SB = BN + 8;       // 136 elems
    constexpr int WM = BM / 2;
    constexpr int MTI = WM / 16;
    constexpr int NCH = K / BK;
    constexpr int WCP = BM * BK / 8 / 256;   // 16B cp.async per plane per thread

    __shared__ __align__(16) __nv_bfloat16 Ah[BM][SA];
    __shared__ __align__(16) __nv_bfloat16 Al[BM][SA];
    __shared__ __align__(16) __nv_bfloat16 Bh[BK][SB];
    __shared__ __align__(16) __nv_bfloat16 Bl[BK][SB];
    __shared__ __align__(16) float maskS[BN];
    __shared__ float aS[K], cS[K];
    __shared__ float rs[BM], rq[BM];

    const int b = blockIdx.z, row0 = blockIdx.y * BM, col0 = blockIdx.x * BN;
    const int tid = threadIdx.x, wid = tid >> 5, lid = tid & 31;
    const int warp_m = wid >> 2, warp_n = wid & 3;
    const int g = lid >> 2, t = lid & 3;

    const float* Xb = X + (size_t)b * K * NVC + col0;
    const float* Rb = (MODE == 2) ? resid + (size_t)b * K * NVC + col0 : nullptr;
    const float* Mb = mask + (size_t)b * NVC + col0;
    float*       Yb = Y + (size_t)b * M * NVC + col0;

    const uint32_t ahS = smem_u32(&Ah[0][0]);
    const uint32_t alS = smem_u32(&Al[0][0]);

    for (int i = tid; i < BN / 4; i += 256)
        reinterpret_cast<float4*>(maskS)[i] = reinterpret_cast<const float4*>(Mb)[i];
    if (MODE != 0) {
        for (int k = tid; k < K; k += 256) {
            float mu  = pssum[k] * CNT_INV;
            float var = fmaf(-mu, mu, pssq[k] * CNT_INV);
            float a   = pg[k] * rsqrtf(var + EPS);
            aS[k] = a;
            cS[k] = fmaf(-mu, a, pb[k]);
        }
    }
    for (int i = tid; i < BM; i += 256) { rs[i] = 0.0f; rq[i] = 0.0f; }
    __syncthreads();

    float acc[MTI][4][4];
#pragma unroll
    for (int mt = 0; mt < MTI; mt++)
#pragma unroll
        for (int nt = 0; nt < 4; nt++)
#pragma unroll
            for (int r = 0; r < 4; r++) acc[mt][nt][r] = 0.0f;

#pragma unroll 1
    for (int ch = 0; ch < NCH; ch++) {
        const int k0 = ch * BK;

        // ---- A (weights): pure 16B async copies from pre-split planes ----
#pragma unroll
        for (int it = 0; it < WCP; it++) {
            const int idx = tid + it * 256;
            const int m  = idx >> 2;          // BK/8 = 4 chunks of 16B per row
            const int kq = idx & 3;
            const size_t goff = (size_t)(row0 + m) * K + k0 + kq * 8;
            const uint32_t soff = (uint32_t)m * (SA * 2) + kq * 16;
            cp_async16(ahS + soff, Whi + goff);
            cp_async16(alS + soff, Wlo + goff);
        }
        CP_COMMIT();

        // ---- B (X chunk): LDG -> BN transform -> packed split -> STS ----
#pragma unroll
        for (int i = tid; i < BK * BN / 4; i += 256) {
            const int kk = i >> 5;
            const int c4 = (i & 31) << 2;
            float4 v = *reinterpret_cast<const float4*>(Xb + (size_t)(k0 + kk) * NVC + c4);
            if (MODE != 0) {
                const float a = aS[k0 + kk], cc = cS[k0 + kk];
                float4 mk = *reinterpret_cast<const float4*>(&maskS[c4]);
                v.x = mk.x > 0.0f ? fmaxf(fmaf(v.x, a, cc), 0.0f) : 0.0f;
                v.y = mk.y > 0.0f ? fmaxf(fmaf(v.y, a, cc), 0.0f) : 0.0f;
                v.z = mk.z > 0.0f ? fmaxf(fmaf(v.z, a, cc), 0.0f) : 0.0f;
                v.w = mk.w > 0.0f ? fmaxf(fmaf(v.w, a, cc), 0.0f) : 0.0f;
                if (MODE == 2) {
                    float4 r = *reinterpret_cast<const float4*>(Rb + (size_t)(k0 + kk) * NVC + c4);
                    v.x += r.x; v.y += r.y; v.z += r.z; v.w += r.w;
                }
            }
            uint2 hi, lo;
            split4f(v, hi, lo);
            *reinterpret_cast<uint2*>(&Bh[kk][c4]) = hi;
            *reinterpret_cast<uint2*>(&Bl[kk][c4]) = lo;
        }
        CP_WAIT0();
        __syncthreads();

        // ---- compute: 2 k16 steps, fragments via direct LDS ----
#pragma unroll
        for (int ks = 0; ks < 2; ks++) {
            const int kb = ks * 16;
            uint32_t bhf[4][2], blf[4][2];
#pragma unroll
            for (int nt = 0; nt < 4; nt++) {
                const int n = warp_n * 32 + nt * 8 + g;
                const __nv_bfloat16* ph = &Bh[kb + 2 * t][n];
                const __nv_bfloat16* pl = &Bl[kb + 2 * t][n];
                bhf[nt][0] = pack2(ph, SB);
                bhf[nt][1] = pack2(ph + 8 * SB, SB);
                blf[nt][0] = pack2(pl, SB);
                blf[nt][1] = pack2(pl + 8 * SB, SB);
            }
#pragma unroll
            for (int mt = 0; mt < MTI; mt++) {
                const int m0 = warp_m * WM + mt * 16;
                const __nv_bfloat16* qh = &Ah[m0 + g][kb + 2 * t];
                const __nv_bfloat16* ql = &Al[m0 + g][kb + 2 * t];
                uint32_t ah[4], al[4];
                ah[0] = ld32(qh);
                ah[1] = ld32(qh + 8 * SA);
                ah[2] = ld32(qh + 8);
                ah[3] = ld32(qh + 8 * SA + 8);
                al[0] = ld32(ql);
                al[1] = ld32(ql + 8 * SA);
                al[2] = ld32(ql + 8);
                al[3] = ld32(ql + 8 * SA + 8);
#pragma unroll
                for (int nt = 0; nt < 4; nt++) {
                    mma16816(acc[mt][nt], ah, bhf[nt]);
                    mma16816(acc[mt][nt], ah, blf[nt]);
                    mma16816(acc[mt][nt], al, bhf[nt]);
                }
            }
        }
        __syncthreads();
    }

    // ---- epilogue: bias + mask, store raw Y (row0 + rowl!), per-row stats ----
#pragma unroll
    for (int mt = 0; mt < MTI; mt++) {
#pragma unroll
        for (int h = 0; h < 2; h++) {
            const int rowl = warp_m * WM + mt * 16 + h * 8 + g;
            const float bv = __ldg(&bias[row0 + rowl]);
            float s = 0.0f, q = 0.0f;
            float* yrow = Yb + (size_t)(row0 + rowl) * NVC;
#pragma unroll
            for (int nt = 0; nt < 4; nt++) {
                const int coll = warp_n * 32 + nt * 8 + t * 2;
                float y0 = (acc[mt][nt][h * 2 + 0] + bv) * maskS[coll];
                float y1 = (acc[mt][nt][h * 2 + 1] + bv) * maskS[coll + 1];
                s += y0 + y1;
                q += y0 * y0 + y1 * y1;
                float2 o; o.x = y0; o.y = y1;
                *reinterpret_cast<float2*>(yrow + coll) = o;
            }
            s += __shfl_xor_sync(0xFFFFFFFF, s, 1);
            s += __shfl_xor_sync(0xFFFFFFFF, s, 2);
            q += __shfl_xor_sync(0xFFFFFFFF, q, 1);
            q += __shfl_xor_sync(0xFFFFFFFF, q, 2);
            if (t == 0) {
                atomicAdd(&rs[rowl], s);
                atomicAdd(&rq[rowl], q);
            }
        }
    }
    __syncthreads();
    for (int i = tid; i < BM; i += 256) {
        atomicAdd(&ssum[row0 + i], rs[i]);
        atomicAdd(&ssq[row0 + i], rq[i]);
    }
}

// out = feats + bnmask_o(rawO) + bnmask_f(rawF)
__global__ void __launch_bounds__(256)
final_fuse(const float* __restrict__ rawO, const float* __restrict__ rawF,
           const float* __restrict__ feats, const float* __restrict__ mask,
           const float* __restrict__ st,
           const float* __restrict__ go, const float* __restrict__ bno,
           const float* __restrict__ gf, const float* __restrict__ bnf,
           float* __restrict__ out)
{
    size_t i = (size_t)blockIdx.x * blockDim.x + threadIdx.x;
    constexpr size_t TOT4 = (size_t)NB * 256 * NVC / 4;
    if (i >= TOT4) return;
    size_t e = i * 4;
    int col = (int)(e % NVC);
    size_t bm = e / NVC;
    int m = (int)(bm % 256);
    int b = (int)(bm / 256);

    float muo  = st[640 + m] * CNT_INV;
    float varo = fmaf(-muo, muo, st[896 + m] * CNT_INV);
    float ao   = go[m] * rsqrtf(varo + EPS);
    float co   = fmaf(-muo, ao, bno[m]);
    float muf  = st[1152 + m] * CNT_INV;
    float varf = fmaf(-muf, muf, st[1408 + m] * CNT_INV);
    float af   = gf[m] * rsqrtf(varf + EPS);
    float cf   = fmaf(-muf, af, bnf[m]);

    float4 o4 = *reinterpret_cast<const float4*>(rawO + e);
    float4 f4 = *reinterpret_cast<const float4*>(rawF + e);
    float4 ft = *reinterpret_cast<const float4*>(feats + e);
    float4 mk = *reinterpret_cast<const float4*>(mask + (size_t)b * NVC + col);

    float4 r;
    r.x = ft.x + (mk.x > 0.0f ? fmaxf(fmaf(o4.x, ao, co), 0.0f) + fmaxf(fmaf(f4.x, af, cf), 0.0f) : 0.0f);
    r.y = ft.y + (mk.y > 0.0f ? fmaxf(fmaf(o4.y, ao, co), 0.0f) + fmaxf(fmaf(f4.y, af, cf), 0.0f) : 0.0f);
    r.z = ft.z + (mk.z > 0.0f ? fmaxf(fmaf(o4.z, ao, co), 0.0f) + fmaxf(fmaf(f4.z, af, cf), 0.0f) : 0.0f);
    r.w = ft.w + (mk.w > 0.0f ? fmaxf(fmaf(o4.w, ao, co), 0.0f) + fmaxf(fmaf(f4.w, af, cf), 0.0f) : 0.0f);
    *reinterpret_cast<float4*>(out + e) = r;
}

extern "C" void kernel_launch(void* const* d_in, const int* in_sizes, int n_in,
                              void* d_out, int out_size)
{
    const float* feats = (const float*)d_in[0];
    const float* mask  = (const float*)d_in[1];
    const float* We    = (const float*)d_in[2];
    const float* be    = (const float*)d_in[3];
    const float* ge    = (const float*)d_in[4];
    const float* bne   = (const float*)d_in[5];
    const float* Wa    = (const float*)d_in[6];
    const float* ba    = (const float*)d_in[7];
    const float* ga    = (const float*)d_in[8];
    const float* bna   = (const float*)d_in[9];
    const float* Wo    = (const float*)d_in[10];
    const float* bo    = (const float*)d_in[11];
    const float* go    = (const float*)d_in[12];
    const float* bno   = (const float*)d_in[13];
    const float* Wf    = (const float*)d_in[14];
    const float* bf    = (const float*)d_in[15];
    const float* gf    = (const float*)d_in[16];
    const float* bnf   = (const float*)d_in[17];
    float* out = (float*)d_out;

    float *emb, *bufa, *bufb, *st;
    __nv_bfloat16 *whi, *wlo;
    cudaGetSymbolAddress((void**)&emb,  g_emb);
    cudaGetSymbolAddress((void**)&bufa, g_bufa);
    cudaGetSymbolAddress((void**)&bufb, g_bufb);
    cudaGetSymbolAddress((void**)&st,   g_stats);
    cudaGetSymbolAddress((void**)&whi,  g_whi);
    cudaGetSymbolAddress((void**)&wlo,  g_wlo);

    zero_stats<<<8, 256>>>();
    split_weights<<<640, 256>>>(We, Wa, Wo, Wf);

    // L1 (e): rawE = We @ feats + be, masked
    mma_layer<64, 256, 64, 0><<<dim3(NVC / 128, 1, NB), 256>>>(
        feats, whi + WOFF_E, wlo + WOFF_E, be, mask,
        nullptr, nullptr, nullptr, nullptr, nullptr,
        emb, st + 0, st + 64);

    // L2 (v-slice of a): X = bn_e(rawE); rawV = Wa_v @ X + ba_v, masked
    mma_layer<256, 64, 128, 1><<<dim3(NVC / 128, 2, NB), 256>>>(
        emb, whi + WOFF_A, wlo + WOFF_A, ba + 512, mask,
        st + 0, st + 64, ge, bne, nullptr,
        bufa, st + 128, st + 384);

    // L3 (o): X = bn_v(rawV); rawO = Wo @ X + bo, masked
    mma_layer<256, 256, 128, 1><<<dim3(NVC / 128, 2, NB), 256>>>(
        bufa, whi + WOFF_O, wlo + WOFF_O, bo, mask,
        st + 128, st + 384, ga + 512, bna + 512, nullptr,
        bufb, st + 640, st + 896);

    // L4 (f): X = feats + bn_o(rawO); rawF = Wf @ X + bf, masked
    mma_layer<256, 256, 128, 2><<<dim3(NVC / 128, 2, NB), 256>>>(
        bufb, whi + WOFF_F, wlo + WOFF_F, bf, mask,
        st + 640, st + 896, go, bno, feats,
        bufa, st + 1152, st + 1408);

    // out = feats + bn_o(rawO) + bn_f(rawF)
    final_fuse<<<(NB * 256 * NVC / 4 + 255) / 256, 256>>>(
        bufb, bufa, feats, mask, st, go, bno, gf, bnf, out);
}

// round 10
// speedup vs baseline: 2.8336x; 1.0261x over previous
#include <cuda_runtime.h>
#include <cuda_bf16.h>
#include <cstdint>

// Shapes: B=8, C=256, N=1024, V=12. NVC = N*V = 12288.
// Identity: attention output == v (softmax over j sums to 1; j only indexes attn),
// so the net is 4 masked-batchstat-BN 1x1 convs (GEMMs) + residuals.
// Round 10: round-9 pipeline (pre-split W + cp.async, packed cvt splits) with
// ldmatrix.x4 fragment loads replacing 64 scalar LDS per k16-step.

#define NVC 12288
#define NB 8
#define CNT_INV (1.0f/98304.0f)
#define EPS 1e-5f

__device__ float g_emb[NB * 64 * NVC];
__device__ float g_bufa[NB * 256 * NVC];
__device__ float g_bufb[NB * 256 * NVC];
__device__ float g_stats[2048];
// pre-split weight planes: We[16384] | Wa_v[16384] | Wo[65536] | Wf[65536]
__device__ __nv_bfloat16 g_whi[163840];
__device__ __nv_bfloat16 g_wlo[163840];

#define WOFF_E  0
#define WOFF_A  16384
#define WOFF_O  32768
#define WOFF_F  98304

__global__ void zero_stats() {
    int i = blockIdx.x * blockDim.x + threadIdx.x;
    if (i < 2048) g_stats[i] = 0.0f;
}

__global__ void split_weights(const float* __restrict__ We, const float* __restrict__ Wa,
                              const float* __restrict__ Wo, const float* __restrict__ Wf)
{
    int i = blockIdx.x * blockDim.x + threadIdx.x;
    if (i >= 163840) return;
    float w;
    if (i < 16384)       w = We[i];
    else if (i < 32768)  w = Wa[512 * 64 + (i - 16384)];
    else if (i < 98304)  w = Wo[i - 32768];
    else                 w = Wf[i - 98304];
    __nv_bfloat16 h = __float2bfloat16(w);
    g_whi[i] = h;
    g_wlo[i] = __float2bfloat16(w - __bfloat162float(h));
}

__device__ __forceinline__ uint32_t smem_u32(const void* p) {
    uint32_t a;
    asm("{ .reg .u64 t; cvta.to.shared.u64 t, %1; cvt.u32.u64 %0, t; }" : "=r"(a) : "l"(p));
    return a;
}
__device__ __forceinline__ void cp_async16(uint32_t dst, const void* src) {
    asm volatile("cp.async.cg.shared.global [%0], [%1], 16;" :: "r"(dst), "l"(src));
}
#define CP_COMMIT() asm volatile("cp.async.commit_group;" ::: "memory")
#define CP_WAIT0()  asm volatile("cp.async.wait_group 0;" ::: "memory")

#define LDSM_X4(r0, r1, r2, r3, addr) \
    asm volatile("ldmatrix.sync.aligned.m8n8.x4.shared.b16 {%0,%1,%2,%3}, [%4];" \
        : "=r"(r0), "=r"(r1), "=r"(r2), "=r"(r3) : "r"(addr))
#define LDSM_X4T(r0, r1, r2, r3, addr) \
    asm volatile("ldmatrix.sync.aligned.m8n8.x4.trans.shared.b16 {%0,%1,%2,%3}, [%4];" \
        : "=r"(r0), "=r"(r1), "=r"(r2), "=r"(r3) : "r"(addr))

__device__ __forceinline__ void mma16816(float* d, const uint32_t* a, const uint32_t* b) {
    asm volatile("mma.sync.aligned.m16n8k16.row.col.f32.bf16.bf16.f32 "
        "{%0,%1,%2,%3}, {%4,%5,%6,%7}, {%8,%9}, {%0,%1,%2,%3};"
        : "+f"(d[0]), "+f"(d[1]), "+f"(d[2]), "+f"(d[3])
        : "r"(a[0]), "r"(a[1]), "r"(a[2]), "r"(a[3]), "r"(b[0]), "r"(b[1]));
}

__device__ __forceinline__ uint32_t cvt2(float h, float l) {
    uint32_t r;
    asm("cvt.rn.bf16x2.f32 %0, %1, %2;" : "=r"(r) : "f"(h), "f"(l));
    return r;
}
__device__ __forceinline__ void split4f(float4 v, uint2& hi, uint2& lo) {
    uint32_t h01 = cvt2(v.y, v.x);
    uint32_t h23 = cvt2(v.w, v.z);
    float f0 = __uint_as_float(h01 << 16);
    float f1 = __uint_as_float(h01 & 0xFFFF0000u);
    float f2 = __uint_as_float(h23 << 16);
    float f3 = __uint_as_float(h23 & 0xFFFF0000u);
    uint32_t l01 = cvt2(v.y - f1, v.x - f0);
    uint32_t l23 = cvt2(v.w - f3, v.z - f2);
    hi.x = h01; hi.y = h23;
    lo.x = l01; lo.y = l23;
}

// One layer: Y[b,m,col] = (sum_k W[m,k]*g(X)[b,k,col] + bias[m]) * mask, plus
// per-channel sum/sumsq. g(): MODE 0=identity, 1=BN+relu+mask, 2=that+resid.
template<int M, int K, int BM, int MODE>
__global__ void __launch_bounds__(256, 2)
mma_layer(const float* __restrict__ X,
          const __nv_bfloat16* __restrict__ Whi, const __nv_bfloat16* __restrict__ Wlo,
          const float* __restrict__ bias, const float* __restrict__ mask,
          const float* __restrict__ pssum, const float* __restrict__ pssq,
          const float* __restrict__ pg, const float* __restrict__ pb,
          const float* __restrict__ resid,
          float* __restrict__ Y, float* __restrict__ ssum, float* __restrict__ ssq)
{
    constexpr int BN = 128, BK = 32;
    constexpr int SA = BK + 8;       // 40 elems, 80B row stride (16B aligned, 5i%8 banks)
    constexpr int SB = BN + 8;       // 136 elems, 272B row stride (17i%8 banks)
    constexpr int WM = BM / 2;
    constexpr int MTI = WM / 16;
    constexpr int NCH = K / BK;
    constexpr int WCP = BM * BK / 8 / 256;

    __shared__ __align__(16) __nv_bfloat16 Ah[BM][SA];
    __shared__ __align__(16) __nv_bfloat16 Al[BM][SA];
    __shared__ __align__(16) __nv_bfloat16 Bh[BK][SB];
    __shared__ __align__(16) __nv_bfloat16 Bl[BK][SB];
    __shared__ __align__(16) float maskS[BN];
    __shared__ float aS[K], cS[K];
    __shared__ float rs[BM], rq[BM];

    const int b = blockIdx.z, row0 = blockIdx.y * BM, col0 = blockIdx.x * BN;
    const int tid = threadIdx.x, wid = tid >> 5, lid = tid & 31;
    const int warp_m = wid >> 2, warp_n = wid & 3;
    const int g = lid >> 2, t = lid & 3;
    const int lq = lid >> 3, lr = lid & 7;

    const float* Xb = X + (size_t)b * K * NVC + col0;
    const float* Rb = (MODE == 2) ? resid + (size_t)b * K * NVC + col0 : nullptr;
    const float* Mb = mask + (size_t)b * NVC + col0;
    float*       Yb = Y + (size_t)b * M * NVC + col0;

    const uint32_t ahS = smem_u32(&Ah[0][0]);
    const uint32_t alS = smem_u32(&Al[0][0]);

    for (int i = tid; i < BN / 4; i += 256)
        reinterpret_cast<float4*>(maskS)[i] = reinterpret_cast<const float4*>(Mb)[i];
    if (MODE != 0) {
        for (int k = tid; k < K; k += 256) {
            float mu  = pssum[k] * CNT_INV;
            float var = fmaf(-mu, mu, pssq[k] * CNT_INV);
            float a   = pg[k] * rsqrtf(var + EPS);
            aS[k] = a;
            cS[k] = fmaf(-mu, a, pb[k]);
        }
    }
    for (int i = tid; i < BM; i += 256) { rs[i] = 0.0f; rq[i] = 0.0f; }
    __syncthreads();

    float acc[MTI][4][4];
#pragma unroll
    for (int mt = 0; mt < MTI; mt++)
#pragma unroll
        for (int nt = 0; nt < 4; nt++)
#pragma unroll
            for (int r = 0; r < 4; r++) acc[mt][nt][r] = 0.0f;

#pragma unroll 1
    for (int ch = 0; ch < NCH; ch++) {
        const int k0 = ch * BK;

        // ---- A (weights): pure 16B async copies from pre-split planes ----
#pragma unroll
        for (int it = 0; it < WCP; it++) {
            const int idx = tid + it * 256;
            const int m  = idx >> 2;
            const int kq = idx & 3;
            const size_t goff = (size_t)(row0 + m) * K + k0 + kq * 8;
            const uint32_t soff = (uint32_t)m * (SA * 2) + kq * 16;
            cp_async16(ahS + soff, Whi + goff);
            cp_async16(alS + soff, Wlo + goff);
        }
        CP_COMMIT();

        // ---- B (X chunk): LDG -> BN transform -> packed split -> STS ----
#pragma unroll
        for (int i = tid; i < BK * BN / 4; i += 256) {
            const int kk = i >> 5;
            const int c4 = (i & 31) << 2;
            float4 v = *reinterpret_cast<const float4*>(Xb + (size_t)(k0 + kk) * NVC + c4);
            if (MODE != 0) {
                const float a = aS[k0 + kk], cc = cS[k0 + kk];
                float4 mk = *reinterpret_cast<const float4*>(&maskS[c4]);
                v.x = mk.x > 0.0f ? fmaxf(fmaf(v.x, a, cc), 0.0f) : 0.0f;
                v.y = mk.y > 0.0f ? fmaxf(fmaf(v.y, a, cc), 0.0f) : 0.0f;
                v.z = mk.z > 0.0f ? fmaxf(fmaf(v.z, a, cc), 0.0f) : 0.0f;
                v.w = mk.w > 0.0f ? fmaxf(fmaf(v.w, a, cc), 0.0f) : 0.0f;
                if (MODE == 2) {
                    float4 r = *reinterpret_cast<const float4*>(Rb + (size_t)(k0 + kk) * NVC + c4);
                    v.x += r.x; v.y += r.y; v.z += r.z; v.w += r.w;
                }
            }
            uint2 hi, lo;
            split4f(v, hi, lo);
            *reinterpret_cast<uint2*>(&Bh[kk][c4]) = hi;
            *reinterpret_cast<uint2*>(&Bl[kk][c4]) = lo;
        }
        CP_WAIT0();
        __syncthreads();

        // ---- compute: 2 k16 steps, fragments via ldmatrix ----
#pragma unroll
        for (int ks = 0; ks < 2; ks++) {
            const int kb = ks * 16;
            // B frags: x4.trans covers 16 n per instr; matrices =
            // {k0-7/n0-7, k8-15/n0-7, k0-7/n8-15, k8-15/n8-15}
            uint32_t bh[4][2], bl[4][2];
#pragma unroll
            for (int p = 0; p < 2; p++) {
                const int nb = warp_n * 32 + p * 16;
                const int brow = kb + (lq & 1) * 8 + lr;
                const int bcol = nb + (lq >> 1) * 8;
                uint32_t r0, r1, r2, r3;
                LDSM_X4T(r0, r1, r2, r3, smem_u32(&Bh[brow][bcol]));
                bh[2 * p][0] = r0; bh[2 * p][1] = r1;
                bh[2 * p + 1][0] = r2; bh[2 * p + 1][1] = r3;
                LDSM_X4T(r0, r1, r2, r3, smem_u32(&Bl[brow][bcol]));
                bl[2 * p][0] = r0; bl[2 * p][1] = r1;
                bl[2 * p + 1][0] = r2; bl[2 * p + 1][1] = r3;
            }
#pragma unroll
            for (int mt = 0; mt < MTI; mt++) {
                const int m0 = warp_m * WM + mt * 16;
                const int arow = m0 + (lq & 1) * 8 + lr;
                const int acol = kb + (lq >> 1) * 8;
                uint32_t ah[4], al[4];
                LDSM_X4(ah[0], ah[1], ah[2], ah[3], smem_u32(&Ah[arow][acol]));
                LDSM_X4(al[0], al[1], al[2], al[3], smem_u32(&Al[arow][acol]));
#pragma unroll
                for (int nt = 0; nt < 4; nt++) {
                    mma16816(acc[mt][nt], ah, bh[nt]);
                    mma16816(acc[mt][nt], ah, bl[nt]);
                    mma16816(acc[mt][nt], al, bh[nt]);
                }
            }
        }
        __syncthreads();
    }

    // ---- epilogue: bias + mask, store raw Y (row0 + rowl), per-row stats ----
#pragma unroll
    for (int mt = 0; mt < MTI; mt++) {
#pragma unroll
        for (int h = 0; h < 2; h++) {
            const int rowl = warp_m * WM + mt * 16 + h * 8 + g;
            const float bv = __ldg(&bias[row0 + rowl]);
            float s = 0.0f, q = 0.0f;
            float* yrow = Yb + (size_t)(row0 + rowl) * NVC;
#pragma unroll
            for (int nt = 0; nt < 4; nt++) {
                const int coll = warp_n * 32 + nt * 8 + t * 2;
                float y0 = (acc[mt][nt][h * 2 + 0] + bv) * maskS[coll];
                float y1 = (acc[mt][nt][h * 2 + 1] + bv) * maskS[coll + 1];
                s += y0 + y1;
                q += y0 * y0 + y1 * y1;
                float2 o; o.x = y0; o.y = y1;
                *reinterpret_cast<float2*>(yrow + coll) = o;
            }
            s += __shfl_xor_sync(0xFFFFFFFF, s, 1);
            s += __shfl_xor_sync(0xFFFFFFFF, s, 2);
            q += __shfl_xor_sync(0xFFFFFFFF, q, 1);
            q += __shfl_xor_sync(0xFFFFFFFF, q, 2);
            if (t == 0) {
                atomicAdd(&rs[rowl], s);
                atomicAdd(&rq[rowl], q);
            }
        }
    }
    __syncthreads();
    for (int i = tid; i < BM; i += 256) {
        atomicAdd(&ssum[row0 + i], rs[i]);
        atomicAdd(&ssq[row0 + i], rq[i]);
    }
}

// out = feats + bnmask_o(rawO) + bnmask_f(rawF)
__global__ void __launch_bounds__(256)
final_fuse(const float* __restrict__ rawO, const float* __restrict__ rawF,
           const float* __restrict__ feats, const float* __restrict__ mask,
           const float* __restrict__ st,
           const float* __restrict__ go, const float* __restrict__ bno,
           const float* __restrict__ gf, const float* __restrict__ bnf,
           float* __restrict__ out)
{
    size_t i = (size_t)blockIdx.x * blockDim.x + threadIdx.x;
    constexpr size_t TOT4 = (size_t)NB * 256 * NVC / 4;
    if (i >= TOT4) return;
    size_t e = i * 4;
    int col = (int)(e % NVC);
    size_t bm = e / NVC;
    int m = (int)(bm % 256);
    int b = (int)(bm / 256);

    float muo  = st[640 + m] * CNT_INV;
    float varo = fmaf(-muo, muo, st[896 + m] * CNT_INV);
    float ao   = go[m] * rsqrtf(varo + EPS);
    float co   = fmaf(-muo, ao, bno[m]);
    float muf  = st[1152 + m] * CNT_INV;
    float varf = fmaf(-muf, muf, st[1408 + m] * CNT_INV);
    float af   = gf[m] * rsqrtf(varf + EPS);
    float cf   = fmaf(-muf, af, bnf[m]);

    float4 o4 = *reinterpret_cast<const float4*>(rawO + e);
    float4 f4 = *reinterpret_cast<const float4*>(rawF + e);
    float4 ft = *reinterpret_cast<const float4*>(feats + e);
    float4 mk = *reinterpret_cast<const float4*>(mask + (size_t)b * NVC + col);

    float4 r;
    r.x = ft.x + (mk.x > 0.0f ? fmaxf(fmaf(o4.x, ao, co), 0.0f) + fmaxf(fmaf(f4.x, af, cf), 0.0f) : 0.0f);
    r.y = ft.y + (mk.y > 0.0f ? fmaxf(fmaf(o4.y, ao, co), 0.0f) + fmaxf(fmaf(f4.y, af, cf), 0.0f) : 0.0f);
    r.z = ft.z + (mk.z > 0.0f ? fmaxf(fmaf(o4.z, ao, co), 0.0f) + fmaxf(fmaf(f4.z, af, cf), 0.0f) : 0.0f);
    r.w = ft.w + (mk.w > 0.0f ? fmaxf(fmaf(o4.w, ao, co), 0.0f) + fmaxf(fmaf(f4.w, af, cf), 0.0f) : 0.0f);
    *reinterpret_cast<float4*>(out + e) = r;
}

extern "C" void kernel_launch(void* const* d_in, const int* in_sizes, int n_in,
                              void* d_out, int out_size)
{
    const float* feats = (const float*)d_in[0];
    const float* mask  = (const float*)d_in[1];
    const float* We    = (const float*)d_in[2];
    const float* be    = (const float*)d_in[3];
    const float* ge    = (const float*)d_in[4];
    const float* bne   = (const float*)d_in[5];
    const float* Wa    = (const float*)d_in[6];
    const float* ba    = (const float*)d_in[7];
    const float* ga    = (const float*)d_in[8];
    const float* bna   = (const float*)d_in[9];
    const float* Wo    = (const float*)d_in[10];
    const float* bo    = (const float*)d_in[11];
    const float* go    = (const float*)d_in[12];
    const float* bno   = (const float*)d_in[13];
    const float* Wf    = (const float*)d_in[14];
    const float* bf    = (const float*)d_in[15];
    const float* gf    = (const float*)d_in[16];
    const float* bnf   = (const float*)d_in[17];
    float* out = (float*)d_out;

    float *emb, *bufa, *bufb, *st;
    __nv_bfloat16 *whi, *wlo;
    cudaGetSymbolAddress((void**)&emb,  g_emb);
    cudaGetSymbolAddress((void**)&bufa, g_bufa);
    cudaGetSymbolAddress((void**)&bufb, g_bufb);
    cudaGetSymbolAddress((void**)&st,   g_stats);
    cudaGetSymbolAddress((void**)&whi,  g_whi);
    cudaGetSymbolAddress((void**)&wlo,  g_wlo);

    zero_stats<<<8, 256>>>();
    split_weights<<<640, 256>>>(We, Wa, Wo, Wf);

    // L1 (e): rawE = We @ feats + be, masked
    mma_layer<64, 256, 64, 0><<<dim3(NVC / 128, 1, NB), 256>>>(
        feats, whi + WOFF_E, wlo + WOFF_E, be, mask,
        nullptr, nullptr, nullptr, nullptr, nullptr,
        emb, st + 0, st + 64);

    // L2 (v-slice of a): X = bn_e(rawE); rawV = Wa_v @ X + ba_v, masked
    mma_layer<256, 64, 128, 1><<<dim3(NVC / 128, 2, NB), 256>>>(
        emb, whi + WOFF_A, wlo + WOFF_A, ba + 512, mask,
        st + 0, st + 64, ge, bne, nullptr,
        bufa, st + 128, st + 384);

    // L3 (o): X = bn_v(rawV); rawO = Wo @ X + bo, masked
    mma_layer<256, 256, 128, 1><<<dim3(NVC / 128, 2, NB), 256>>>(
        bufa, whi + WOFF_O, wlo + WOFF_O, bo, mask,
        st + 128, st + 384, ga + 512, bna + 512, nullptr,
        bufb, st + 640, st + 896);

    // L4 (f): X = feats + bn_o(rawO); rawF = Wf @ X + bf, masked
    mma_layer<256, 256, 128, 2><<<dim3(NVC / 128, 2, NB), 256>>>(
        bufb, whi + WOFF_F, wlo + WOFF_F, bf, mask,
        st + 640, st + 896, go, bno, feats,
        bufa, st + 1152, st + 1408);

    // out = feats + bn_o(rawO) + bn_f(rawF)
    final_fuse<<<(NB * 256 * NVC / 4 + 255) / 256, 256>>>(
        bufb, bufa, feats, mask, st, go, bno, gf, bnf, out);
}

// round 11
// speedup vs baseline: 3.0844x; 1.0885x over previous
#include <cuda_runtime.h>
#include <cuda_bf16.h>
#include <cstdint>

// Shapes: B=8, C=256, N=1024, V=12. NVC = N*V = 12288.
// Identity: attention output == v (softmax over j sums to 1; j only indexes attn),
// so the net is 4 masked-batchstat-BN 1x1 convs (GEMMs) + residuals.
// Round 11: cp.async double-buffered pipeline. Raw X chunks staged in smem fp32
// (double buffer) + A planes double-buffered; transform/split is smem->smem and
// all global latency overlaps compute. ldmatrix + split-bf16 mma.sync mainloop.

#define NVC 12288
#define NB 8
#define CNT_INV (1.0f/98304.0f)
#define EPS 1e-5f

__device__ float g_emb[NB * 64 * NVC];
__device__ float g_bufa[NB * 256 * NVC];
__device__ float g_bufb[NB * 256 * NVC];
__device__ float g_stats[2048];
__device__ __nv_bfloat16 g_whi[163840];
__device__ __nv_bfloat16 g_wlo[163840];

#define WOFF_E  0
#define WOFF_A  16384
#define WOFF_O  32768
#define WOFF_F  98304

__global__ void zero_stats() {
    int i = blockIdx.x * blockDim.x + threadIdx.x;
    if (i < 2048) g_stats[i] = 0.0f;
}

__global__ void split_weights(const float* __restrict__ We, const float* __restrict__ Wa,
                              const float* __restrict__ Wo, const float* __restrict__ Wf)
{
    int i = blockIdx.x * blockDim.x + threadIdx.x;
    if (i >= 163840) return;
    float w;
    if (i < 16384)       w = We[i];
    else if (i < 32768)  w = Wa[512 * 64 + (i - 16384)];
    else if (i < 98304)  w = Wo[i - 32768];
    else                 w = Wf[i - 98304];
    __nv_bfloat16 h = __float2bfloat16(w);
    g_whi[i] = h;
    g_wlo[i] = __float2bfloat16(w - __bfloat162float(h));
}

__device__ __forceinline__ uint32_t smem_u32(const void* p) {
    uint32_t a;
    asm("{ .reg .u64 t; cvta.to.shared.u64 t, %1; cvt.u32.u64 %0, t; }" : "=r"(a) : "l"(p));
    return a;
}
__device__ __forceinline__ void cp_async16(uint32_t dst, const void* src) {
    asm volatile("cp.async.cg.shared.global [%0], [%1], 16;" :: "r"(dst), "l"(src));
}
#define CP_COMMIT() asm volatile("cp.async.commit_group;" ::: "memory")
#define CP_WAIT0()  asm volatile("cp.async.wait_group 0;" ::: "memory")

#define LDSM_X4(r0, r1, r2, r3, addr) \
    asm volatile("ldmatrix.sync.aligned.m8n8.x4.shared.b16 {%0,%1,%2,%3}, [%4];" \
        : "=r"(r0), "=r"(r1), "=r"(r2), "=r"(r3) : "r"(addr))
#define LDSM_X4T(r0, r1, r2, r3, addr) \
    asm volatile("ldmatrix.sync.aligned.m8n8.x4.trans.shared.b16 {%0,%1,%2,%3}, [%4];" \
        : "=r"(r0), "=r"(r1), "=r"(r2), "=r"(r3) : "r"(addr))

__device__ __forceinline__ void mma16816(float* d, const uint32_t* a, const uint32_t* b) {
    asm volatile("mma.sync.aligned.m16n8k16.row.col.f32.bf16.bf16.f32 "
        "{%0,%1,%2,%3}, {%4,%5,%6,%7}, {%8,%9}, {%0,%1,%2,%3};"
        : "+f"(d[0]), "+f"(d[1]), "+f"(d[2]), "+f"(d[3])
        : "r"(a[0]), "r"(a[1]), "r"(a[2]), "r"(a[3]), "r"(b[0]), "r"(b[1]));
}

__device__ __forceinline__ uint32_t cvt2(float h, float l) {
    uint32_t r;
    asm("cvt.rn.bf16x2.f32 %0, %1, %2;" : "=r"(r) : "f"(h), "f"(l));
    return r;
}
__device__ __forceinline__ void split4f(float4 v, uint2& hi, uint2& lo) {
    uint32_t h01 = cvt2(v.y, v.x);
    uint32_t h23 = cvt2(v.w, v.z);
    float f0 = __uint_as_float(h01 << 16);
    float f1 = __uint_as_float(h01 & 0xFFFF0000u);
    float f2 = __uint_as_float(h23 << 16);
    float f3 = __uint_as_float(h23 & 0xFFFF0000u);
    uint32_t l01 = cvt2(v.y - f1, v.x - f0);
    uint32_t l23 = cvt2(v.w - f3, v.z - f2);
    hi.x = h01; hi.y = h23;
    lo.x = l01; lo.y = l23;
}

// smem layout helper (bytes)
template<int BM, int K>
struct SmemCfg {
    static constexpr int BN = 128, BK = 32, SA = 40, SB = 136;
    static constexpr int XRAW = 2 * BK * BN * 4;            // 32768
    static constexpr int APL  = 2 * BM * SA * 2;            // per plane (hi or lo)
    static constexpr int BPL  = BK * SB * 2;                // 8704
    static constexpr int O_AH = XRAW;
    static constexpr int O_AL = O_AH + APL;
    static constexpr int O_BH = O_AL + APL;
    static constexpr int O_BL = O_BH + BPL;
    static constexpr int O_MK = O_BL + BPL;                 // mask BN*4
    static constexpr int O_AS = O_MK + BN * 4;              // aS K*4
    static constexpr int O_CS = O_AS + K * 4;
    static constexpr int O_RS = O_CS + K * 4;
    static constexpr int O_RQ = O_RS + BM * 4;
    static constexpr int TOTAL = O_RQ + BM * 4;
};

// One layer: Y[b,m,col] = (sum_k W[m,k]*g(X)[b,k,col] + bias[m]) * mask, plus
// per-channel sum/sumsq. g(): MODE 0=identity, 1=BN+relu+mask, 2=that+resid.
template<int M, int K, int BM, int MODE>
__global__ void __launch_bounds__(256, 2)
mma_layer(const float* __restrict__ X,
          const __nv_bfloat16* __restrict__ Whi, const __nv_bfloat16* __restrict__ Wlo,
          const float* __restrict__ bias, const float* __restrict__ mask,
          const float* __restrict__ pssum, const float* __restrict__ pssq,
          const float* __restrict__ pg, const float* __restrict__ pb,
          const float* __restrict__ resid,
          float* __restrict__ Y, float* __restrict__ ssum, float* __restrict__ ssq)
{
    using CFG = SmemCfg<BM, K>;
    constexpr int BN = 128, BK = 32, SA = 40, SB = 136;
    constexpr int WM = BM / 2;
    constexpr int MTI = WM / 16;
    constexpr int NCH = K / BK;
    constexpr int ACP = BM * BK / 8 / 256;   // 16B cp.async per plane per thread

    extern __shared__ char sm[];
    float* Xraw = reinterpret_cast<float*>(sm);
    __nv_bfloat16* Ah = reinterpret_cast<__nv_bfloat16*>(sm + CFG::O_AH);
    __nv_bfloat16* Al = reinterpret_cast<__nv_bfloat16*>(sm + CFG::O_AL);
    __nv_bfloat16* Bh = reinterpret_cast<__nv_bfloat16*>(sm + CFG::O_BH);
    __nv_bfloat16* Bl = reinterpret_cast<__nv_bfloat16*>(sm + CFG::O_BL);
    float* maskS = reinterpret_cast<float*>(sm + CFG::O_MK);
    float* aS    = reinterpret_cast<float*>(sm + CFG::O_AS);
    float* cS    = reinterpret_cast<float*>(sm + CFG::O_CS);
    float* rs    = reinterpret_cast<float*>(sm + CFG::O_RS);
    float* rq    = reinterpret_cast<float*>(sm + CFG::O_RQ);

    const int b = blockIdx.z, row0 = blockIdx.y * BM, col0 = blockIdx.x * BN;
    const int tid = threadIdx.x, wid = tid >> 5, lid = tid & 31;
    const int warp_m = wid >> 2, warp_n = wid & 3;
    const int g = lid >> 2, t4 = lid & 3;
    const int lq = lid >> 3, lr = lid & 7;

    const float* Xb = X + (size_t)b * K * NVC + col0;
    const float* Rb = (MODE == 2) ? resid + (size_t)b * K * NVC + col0 : nullptr;
    const float* Mb = mask + (size_t)b * NVC + col0;
    float*       Yb = Y + (size_t)b * M * NVC + col0;

    const uint32_t xrS = smem_u32(Xraw);
    const uint32_t ahS = smem_u32(Ah);
    const uint32_t alS = smem_u32(Al);

    // per-thread cp.async coordinates for X (also the transform coordinates)
    // idx = tid + it*256 -> kk = idx>>5, c16 = (idx&31)*4 floats
    // block init
    for (int i = tid; i < BN / 4; i += 256)
        reinterpret_cast<float4*>(maskS)[i] = reinterpret_cast<const float4*>(Mb)[i];
    if (MODE != 0) {
        for (int k = tid; k < K; k += 256) {
            float mu  = pssum[k] * CNT_INV;
            float var = fmaf(-mu, mu, pssq[k] * CNT_INV);
            float a   = pg[k] * rsqrtf(var + EPS);
            aS[k] = a;
            cS[k] = fmaf(-mu, a, pb[k]);
        }
    }
    for (int i = tid; i < BM; i += 256) { rs[i] = 0.0f; rq[i] = 0.0f; }

    float acc[MTI][4][4];
#pragma unroll
    for (int mt = 0; mt < MTI; mt++)
#pragma unroll
        for (int nt = 0; nt < 4; nt++)
#pragma unroll
            for (int r = 0; r < 4; r++) acc[mt][nt][r] = 0.0f;

    // ---- issue group for chunk 0 ----
    auto issue_chunk = [&](int ch) {
        const int buf = ch & 1;
        const int k0 = ch * BK;
        // X raw fp32: BK*BN*4/16 = 1024 chunks -> 4 per thread
#pragma unroll
        for (int it = 0; it < 4; it++) {
            const int idx = tid + it * 256;
            const int kk = idx >> 5;
            const int c16 = (idx & 31) * 4;
            cp_async16(xrS + (uint32_t)(buf * BK * BN + kk * BN + c16) * 4,
                       Xb + (size_t)(k0 + kk) * NVC + c16);
        }
        // A planes
#pragma unroll
        for (int it = 0; it < ACP; it++) {
            const int idx = tid + it * 256;
            const int m  = idx >> 2;
            const int kq = idx & 3;
            const size_t goff = (size_t)(row0 + m) * K + k0 + kq * 8;
            const uint32_t soff = (uint32_t)(buf * BM * SA + m * SA + kq * 8) * 2;
            cp_async16(ahS + soff, Whi + goff);
            cp_async16(alS + soff, Wlo + goff);
        }
        CP_COMMIT();
    };

    issue_chunk(0);
    CP_WAIT0();
    __syncthreads();

#pragma unroll 1
    for (int ch = 0; ch < NCH; ch++) {
        const int buf = ch & 1;
        const int k0 = ch * BK;

        // ---- transform: Xraw[buf] -> Bh/Bl (smem->smem; MODE2 resid from global) ----
        float4 rr[4];
        if (MODE == 2) {
#pragma unroll
            for (int it = 0; it < 4; it++) {
                const int idx = tid + it * 256;
                const int kk = idx >> 5;
                const int c16 = (idx & 31) * 4;
                rr[it] = *reinterpret_cast<const float4*>(Rb + (size_t)(k0 + kk) * NVC + c16);
            }
        }
#pragma unroll
        for (int it = 0; it < 4; it++) {
            const int idx = tid + it * 256;
            const int kk = idx >> 5;
            const int c16 = (idx & 31) * 4;
            float4 v = *reinterpret_cast<const float4*>(&Xraw[buf * BK * BN + kk * BN + c16]);
            if (MODE != 0) {
                const float a = aS[k0 + kk], cc = cS[k0 + kk];
                float4 mk = *reinterpret_cast<const float4*>(&maskS[c16]);
                v.x = mk.x > 0.0f ? fmaxf(fmaf(v.x, a, cc), 0.0f) : 0.0f;
                v.y = mk.y > 0.0f ? fmaxf(fmaf(v.y, a, cc), 0.0f) : 0.0f;
                v.z = mk.z > 0.0f ? fmaxf(fmaf(v.z, a, cc), 0.0f) : 0.0f;
                v.w = mk.w > 0.0f ? fmaxf(fmaf(v.w, a, cc), 0.0f) : 0.0f;
                if (MODE == 2) {
                    v.x += rr[it].x; v.y += rr[it].y; v.z += rr[it].z; v.w += rr[it].w;
                }
            }
            uint2 hi, lo;
            split4f(v, hi, lo);
            *reinterpret_cast<uint2*>(&Bh[kk * SB + c16]) = hi;
            *reinterpret_cast<uint2*>(&Bl[kk * SB + c16]) = lo;
        }
        __syncthreads();

        // ---- prefetch next chunk (lands during compute) ----
        if (ch + 1 < NCH) issue_chunk(ch + 1);

        // ---- compute: 2 k16 steps, ldmatrix fragments ----
#pragma unroll
        for (int ks = 0; ks < 2; ks++) {
            const int kb = ks * 16;
            uint32_t bh[4][2], bl[4][2];
#pragma unroll
            for (int p = 0; p < 2; p++) {
                const int nb = warp_n * 32 + p * 16;
                const int brow = kb + (lq & 1) * 8 + lr;
                const int bcol = nb + (lq >> 1) * 8;
                uint32_t r0, r1, r2, r3;
                LDSM_X4T(r0, r1, r2, r3, smem_u32(&Bh[brow * SB + bcol]));
                bh[2 * p][0] = r0; bh[2 * p][1] = r1;
                bh[2 * p + 1][0] = r2; bh[2 * p + 1][1] = r3;
                LDSM_X4T(r0, r1, r2, r3, smem_u32(&Bl[brow * SB + bcol]));
                bl[2 * p][0] = r0; bl[2 * p][1] = r1;
                bl[2 * p + 1][0] = r2; bl[2 * p + 1][1] = r3;
            }
#pragma unroll
            for (int mt = 0; mt < MTI; mt++) {
                const int m0 = warp_m * WM + mt * 16;
                const int arow = m0 + (lq & 1) * 8 + lr;
                const int acol = kb + (lq >> 1) * 8;
                uint32_t ah[4], al[4];
                LDSM_X4(ah[0], ah[1], ah[2], ah[3],
                        smem_u32(&Ah[buf * BM * SA + arow * SA + acol]));
                LDSM_X4(al[0], al[1], al[2], al[3],
                        smem_u32(&Al[buf * BM * SA + arow * SA + acol]));
#pragma unroll
                for (int nt = 0; nt < 4; nt++) {
                    mma16816(acc[mt][nt], ah, bh[nt]);
                    mma16816(acc[mt][nt], ah, bl[nt]);
                    mma16816(acc[mt][nt], al, bh[nt]);
                }
            }
        }
        if (ch + 1 < NCH) CP_WAIT0();
        __syncthreads();
    }

    // ---- epilogue: bias + mask, store raw Y (row0 + rowl), per-row stats ----
#pragma unroll
    for (int mt = 0; mt < MTI; mt++) {
#pragma unroll
        for (int h = 0; h < 2; h++) {
            const int rowl = warp_m * WM + mt * 16 + h * 8 + g;
            const float bv = __ldg(&bias[row0 + rowl]);
            float s = 0.0f, q = 0.0f;
            float* yrow = Yb + (size_t)(row0 + rowl) * NVC;
#pragma unroll
            for (int nt = 0; nt < 4; nt++) {
                const int coll = warp_n * 32 + nt * 8 + t4 * 2;
                float y0 = (acc[mt][nt][h * 2 + 0] + bv) * maskS[coll];
                float y1 = (acc[mt][nt][h * 2 + 1] + bv) * maskS[coll + 1];
                s += y0 + y1;
                q += y0 * y0 + y1 * y1;
                float2 o; o.x = y0; o.y = y1;
                *reinterpret_cast<float2*>(yrow + coll) = o;
            }
            s += __shfl_xor_sync(0xFFFFFFFF, s, 1);
            s += __shfl_xor_sync(0xFFFFFFFF, s, 2);
            q += __shfl_xor_sync(0xFFFFFFFF, q, 1);
            q += __shfl_xor_sync(0xFFFFFFFF, q, 2);
            if (t4 == 0) {
                atomicAdd(&rs[rowl], s);
                atomicAdd(&rq[rowl], q);
            }
        }
    }
    __syncthreads();
    for (int i = tid; i < BM; i += 256) {
        atomicAdd(&ssum[row0 + i], rs[i]);
        atomicAdd(&ssq[row0 + i], rq[i]);
    }
}

// out = feats + bnmask_o(rawO) + bnmask_f(rawF)
__global__ void __launch_bounds__(256)
final_fuse(const float* __restrict__ rawO, const float* __restrict__ rawF,
           const float* __restrict__ feats, const float* __restrict__ mask,
           const float* __restrict__ st,
           const float* __restrict__ go, const float* __restrict__ bno,
           const float* __restrict__ gf, const float* __restrict__ bnf,
           float* __restrict__ out)
{
    size_t i = (size_t)blockIdx.x * blockDim.x + threadIdx.x;
    constexpr size_t TOT4 = (size_t)NB * 256 * NVC / 4;
    if (i >= TOT4) return;
    size_t e = i * 4;
    int col = (int)(e % NVC);
    size_t bm = e / NVC;
    int m = (int)(bm % 256);
    int b = (int)(bm / 256);

    float muo  = st[640 + m] * CNT_INV;
    float varo = fmaf(-muo, muo, st[896 + m] * CNT_INV);
    float ao   = go[m] * rsqrtf(varo + EPS);
    float co   = fmaf(-muo, ao, bno[m]);
    float muf  = st[1152 + m] * CNT_INV;
    float varf = fmaf(-muf, muf, st[1408 + m] * CNT_INV);
    float af   = gf[m] * rsqrtf(varf + EPS);
    float cf   = fmaf(-muf, af, bnf[m]);

    float4 o4 = *reinterpret_cast<const float4*>(rawO + e);
    float4 f4 = *reinterpret_cast<const float4*>(rawF + e);
    float4 ft = *reinterpret_cast<const float4*>(feats + e);
    float4 mk = *reinterpret_cast<const float4*>(mask + (size_t)b * NVC + col);

    float4 r;
    r.x = ft.x + (mk.x > 0.0f ? fmaxf(fmaf(o4.x, ao, co), 0.0f) + fmaxf(fmaf(f4.x, af, cf), 0.0f) : 0.0f);
    r.y = ft.y + (mk.y > 0.0f ? fmaxf(fmaf(o4.y, ao, co), 0.0f) + fmaxf(fmaf(f4.y, af, cf), 0.0f) : 0.0f);
    r.z = ft.z + (mk.z > 0.0f ? fmaxf(fmaf(o4.z, ao, co), 0.0f) + fmaxf(fmaf(f4.z, af, cf), 0.0f) : 0.0f);
    r.w = ft.w + (mk.w > 0.0f ? fmaxf(fmaf(o4.w, ao, co), 0.0f) + fmaxf(fmaf(f4.w, af, cf), 0.0f) : 0.0f);
    *reinterpret_cast<float4*>(out + e) = r;
}

extern "C" void kernel_launch(void* const* d_in, const int* in_sizes, int n_in,
                              void* d_out, int out_size)
{
    const float* feats = (const float*)d_in[0];
    const float* mask  = (const float*)d_in[1];
    const float* We    = (const float*)d_in[2];
    const float* be    = (const float*)d_in[3];
    const float* ge    = (const float*)d_in[4];
    const float* bne   = (const float*)d_in[5];
    const float* Wa    = (const float*)d_in[6];
    const float* ba    = (const float*)d_in[7];
    const float* ga    = (const float*)d_in[8];
    const float* bna   = (const float*)d_in[9];
    const float* Wo    = (const float*)d_in[10];
    const float* bo    = (const float*)d_in[11];
    const float* go    = (const float*)d_in[12];
    const float* bno   = (const float*)d_in[13];
    const float* Wf    = (const float*)d_in[14];
    const float* bf    = (const float*)d_in[15];
    const float* gf    = (const float*)d_in[16];
    const float* bnf   = (const float*)d_in[17];
    float* out = (float*)d_out;

    float *emb, *bufa, *bufb, *st;
    __nv_bfloat16 *whi, *wlo;
    cudaGetSymbolAddress((void**)&emb,  g_emb);
    cudaGetSymbolAddress((void**)&bufa, g_bufa);
    cudaGetSymbolAddress((void**)&bufb, g_bufb);
    cudaGetSymbolAddress((void**)&st,   g_stats);
    cudaGetSymbolAddress((void**)&whi,  g_whi);
    cudaGetSymbolAddress((void**)&wlo,  g_wlo);

    constexpr int SM1 = SmemCfg<64, 256>::TOTAL;
    constexpr int SM2 = SmemCfg<128, 64>::TOTAL;
    constexpr int SM3 = SmemCfg<128, 256>::TOTAL;
    cudaFuncSetAttribute(mma_layer<64, 256, 64, 0>,
                         cudaFuncAttributeMaxDynamicSharedMemorySize, SM1);
    cudaFuncSetAttribute(mma_layer<256, 64, 128, 1>,
                         cudaFuncAttributeMaxDynamicSharedMemorySize, SM2);
    cudaFuncSetAttribute(mma_layer<256, 256, 128, 1>,
                         cudaFuncAttributeMaxDynamicSharedMemorySize, SM3);
    cudaFuncSetAttribute(mma_layer<256, 256, 128, 2>,
                         cudaFuncAttributeMaxDynamicSharedMemorySize, SM3);

    zero_stats<<<8, 256>>>();
    split_weights<<<640, 256>>>(We, Wa, Wo, Wf);

    // L1 (e): rawE = We @ feats + be, masked
    mma_layer<64, 256, 64, 0><<<dim3(NVC / 128, 1, NB), 256, SM1>>>(
        feats, whi + WOFF_E, wlo + WOFF_E, be, mask,
        nullptr, nullptr, nullptr, nullptr, nullptr,
        emb, st + 0, st + 64);

    // L2 (v-slice of a): X = bn_e(rawE); rawV = Wa_v @ X + ba_v, masked
    mma_layer<256, 64, 128, 1><<<dim3(NVC / 128, 2, NB), 256, SM2>>>(
        emb, whi + WOFF_A, wlo + WOFF_A, ba + 512, mask,
        st + 0, st + 64, ge, bne, nullptr,
        bufa, st + 128, st + 384);

    // L3 (o): X = bn_v(rawV); rawO = Wo @ X + bo, masked
    mma_layer<256, 256, 128, 1><<<dim3(NVC / 128, 2, NB), 256, SM3>>>(
        bufa, whi + WOFF_O, wlo + WOFF_O, bo, mask,
        st + 128, st + 384, ga + 512, bna + 512, nullptr,
        bufb, st + 640, st + 896);

    // L4 (f): X = feats + bn_o(rawO); rawF = Wf @ X + bf, masked
    mma_layer<256, 256, 128, 2><<<dim3(NVC / 128, 2, NB), 256, SM3>>>(
        bufb, whi + WOFF_F, wlo + WOFF_F, bf, mask,
        st + 640, st + 896, go, bno, feats,
        bufa, st + 1152, st + 1408);

    // out = feats + bn_o(rawO) + bn_f(rawF)
    final_fuse<<<(NB * 256 * NVC / 4 + 255) / 256, 256>>>(
        bufb, bufa, feats, mask, st, go, bno, gf, bnf, out);
}